// round 12
// baseline (speedup 1.0000x reference)
#include <cuda_runtime.h>
#include <cuda_bf16.h>
#include <cstdint>

#define HEADS 12
#define SEQ   2048
#define BATCH 4
#define DH    64
#define CDIM  768
#define MTOT  8192   // BATCH*SEQ
#define NQKV ((size_t)BATCH * HEADS * SEQ * DH)

// ---------------- scratch (allocation-free) ----------------
__device__ __align__(16) __nv_bfloat16 g_qhi[NQKV], g_qlo[NQKV];
__device__ __align__(16) __nv_bfloat16 g_khi[NQKV], g_klo[NQKV];
__device__ __align__(16) __nv_bfloat16 g_vhi[NQKV], g_vlo[NQKV];
__device__ __align__(16) __nv_bfloat16 g_a_hi[(size_t)MTOT * CDIM];
__device__ __align__(16) __nv_bfloat16 g_a_lo[(size_t)MTOT * CDIM];
__device__ __align__(16) __nv_bfloat16 g_w_hi[(size_t)3 * CDIM * CDIM];
__device__ __align__(16) __nv_bfloat16 g_w_lo[(size_t)3 * CDIM * CDIM];
__device__ __align__(16) __nv_bfloat16 g_w2_hi[(size_t)CDIM * CDIM];
__device__ __align__(16) __nv_bfloat16 g_w2_lo[(size_t)CDIM * CDIM];

// Q prescale: 1/sqrt(64) * log2(e)
#define QSCALE 0.1803368801111204f

// ---------------- helpers ----------------
__device__ __forceinline__ uint32_t smem_u32(const void* p) {
    uint32_t a;
    asm("{ .reg .u64 t; cvta.to.shared.u64 t, %1; cvt.u32.u64 %0, t; }" : "=r"(a) : "l"(p));
    return a;
}
__device__ __forceinline__ void ldsm4(uint32_t& r0, uint32_t& r1, uint32_t& r2, uint32_t& r3,
                                      uint32_t addr) {
    asm volatile("ldmatrix.sync.aligned.m8n8.x4.shared.b16 {%0,%1,%2,%3}, [%4];"
                 : "=r"(r0), "=r"(r1), "=r"(r2), "=r"(r3) : "r"(addr));
}
__device__ __forceinline__ void ldsm4t(uint32_t& r0, uint32_t& r1, uint32_t& r2, uint32_t& r3,
                                       uint32_t addr) {
    asm volatile("ldmatrix.sync.aligned.m8n8.x4.trans.shared.b16 {%0,%1,%2,%3}, [%4];"
                 : "=r"(r0), "=r"(r1), "=r"(r2), "=r"(r3) : "r"(addr));
}
__device__ __forceinline__ void mma16816(float* c, const uint32_t* a, uint32_t b0, uint32_t b1) {
    asm volatile("mma.sync.aligned.m16n8k16.row.col.f32.bf16.bf16.f32 "
                 "{%0,%1,%2,%3}, {%4,%5,%6,%7}, {%8,%9}, {%0,%1,%2,%3};"
                 : "+f"(c[0]), "+f"(c[1]), "+f"(c[2]), "+f"(c[3])
                 : "r"(a[0]), "r"(a[1]), "r"(a[2]), "r"(a[3]), "r"(b0), "r"(b1));
}
__device__ __forceinline__ __nv_bfloat16 bhi(float x) { return __float2bfloat16(x); }
__device__ __forceinline__ __nv_bfloat16 blo(float x, __nv_bfloat16 h) {
    return __float2bfloat16(x - __bfloat162float(h));
}
__device__ __forceinline__ float ex2f(float x) {
    float y;
    asm("ex2.approx.f32 %0, %1;" : "=f"(y) : "f"(x));
    return y;
}
__device__ __forceinline__ uint32_t packbf(float lo_, float hi_) {
    uint32_t r;
    asm("cvt.rn.bf16x2.f32 %0, %1, %2;" : "=r"(r) : "f"(hi_), "f"(lo_));
    return r;
}

#define CP_ASYNC16(dst, src) \
    asm volatile("cp.async.cg.shared.global [%0], [%1], 16;" :: "r"(dst), "l"(src))
#define CP_COMMIT() asm volatile("cp.async.commit_group;")
#define CP_WAIT1()  asm volatile("cp.async.wait_group 1;")
#define CP_WAIT0()  asm volatile("cp.async.wait_group 0;")

// ---------------------------------------------------------------------------
__global__ void split_kernel(const float4* __restrict__ src,
                             __nv_bfloat162* __restrict__ hi,
                             __nv_bfloat162* __restrict__ lo, int n4)
{
    int i = blockIdx.x * 256 + threadIdx.x;
    if (i < n4) {
        float4 v = src[i];
        __nv_bfloat16 hx = __float2bfloat16(v.x);
        __nv_bfloat16 hy = __float2bfloat16(v.y);
        __nv_bfloat16 hz = __float2bfloat16(v.z);
        __nv_bfloat16 hw = __float2bfloat16(v.w);
        hi[2 * i]     = __nv_bfloat162(hx, hy);
        hi[2 * i + 1] = __nv_bfloat162(hz, hw);
        lo[2 * i]     = __nv_bfloat162(blo(v.x, hx), blo(v.y, hy));
        lo[2 * i + 1] = __nv_bfloat162(blo(v.z, hz), blo(v.w, hw));
    }
}

// ---------------------------------------------------------------------------
// HMMA bf16x3 GEMM v2 (unchanged).
// ---------------------------------------------------------------------------
#define LDT2 40
#define GM_MSZ (128 * LDT2)
#define GAHI 0
#define GALO GM_MSZ
#define GWHI (2 * GM_MSZ)
#define GWLO (3 * GM_MSZ)
#define GM_BUF (4 * GM_MSZ)
#define GEMM_SMEM (2 * GM_BUF * 2)     // 81920 bytes
#define NCHUNK 24

template <int MODE>
__global__ void __launch_bounds__(256, 2)
mma_gemm(const __nv_bfloat16* __restrict__ a_hi, const __nv_bfloat16* __restrict__ a_lo,
         const __nv_bfloat16* __restrict__ w_hi, const __nv_bfloat16* __restrict__ w_lo,
         const float* __restrict__ bias, float* __restrict__ out)
{
    extern __shared__ __nv_bfloat16 sm[];
    const uint32_t smb = smem_u32(sm);
    const int tid  = threadIdx.x;
    const int lane = tid & 31;
    const int wrp  = tid >> 5;
    const int wm   = wrp & 1;
    const int wn   = wrp >> 1;
    const int rowBase = blockIdx.y * 128;
    const int colBase = blockIdx.x * 128;

    const int a_r = lane & 15;
    const int a_k = (lane >> 4) * 8;
    const int b_r = (lane & 7) + ((lane >> 4) << 3);
    const int b_k = ((lane >> 3) & 1) * 8;

    float acc[4][4][4] = {};

    #define LOAD_CHUNK(kk, buf)                                                       \
        do {                                                                          \
            const uint32_t _bb = smb + (uint32_t)((buf) * GM_BUF) * 2;                \
            _Pragma("unroll")                                                         \
            for (int _i = 0; _i < 2; ++_i) {                                          \
                const int _idx = _i * 256 + tid;                                      \
                const int _r = _idx >> 2, _c = _idx & 3;                              \
                const size_t _ga = (size_t)(rowBase + _r) * CDIM + (kk) + _c * 8;     \
                const size_t _gw = (size_t)(colBase + _r) * CDIM + (kk) + _c * 8;     \
                const uint32_t _so = (uint32_t)(_r * LDT2 + _c * 8) * 2;              \
                CP_ASYNC16(_bb + GAHI * 2 + _so, a_hi + _ga);                         \
                CP_ASYNC16(_bb + GALO * 2 + _so, a_lo + _ga);                         \
                CP_ASYNC16(_bb + GWHI * 2 + _so, w_hi + _gw);                         \
                CP_ASYNC16(_bb + GWLO * 2 + _so, w_lo + _gw);                         \
            }                                                                         \
        } while (0)

    LOAD_CHUNK(0, 0);
    CP_COMMIT();

    for (int t = 0; t < NCHUNK; ++t) {
        const int buf = t & 1;
        __syncthreads();
        if (t < NCHUNK - 1) {
            LOAD_CHUNK((t + 1) * 32, buf ^ 1);
            CP_COMMIT();
            CP_WAIT1();
        } else {
            CP_WAIT0();
        }
        __syncthreads();

        const uint32_t ahB = smb + (uint32_t)(buf * GM_BUF + GAHI) * 2;
        const uint32_t alB = smb + (uint32_t)(buf * GM_BUF + GALO) * 2;
        const uint32_t whB = smb + (uint32_t)(buf * GM_BUF + GWHI) * 2;
        const uint32_t wlB = smb + (uint32_t)(buf * GM_BUF + GWLO) * 2;

        #pragma unroll
        for (int ks = 0; ks < 2; ++ks) {
            uint32_t ah[4][4], al[4][4], wh2[2][4], wl2[2][4];
            #pragma unroll
            for (int mt = 0; mt < 4; ++mt) {
                const uint32_t off =
                    (uint32_t)((wm * 64 + mt * 16 + a_r) * LDT2 + ks * 16 + a_k) * 2;
                ldsm4(ah[mt][0], ah[mt][1], ah[mt][2], ah[mt][3], ahB + off);
                ldsm4(al[mt][0], al[mt][1], al[mt][2], al[mt][3], alB + off);
            }
            #pragma unroll
            for (int np2 = 0; np2 < 2; ++np2) {
                const uint32_t off =
                    (uint32_t)((wn * 32 + np2 * 16 + b_r) * LDT2 + ks * 16 + b_k) * 2;
                ldsm4(wh2[np2][0], wh2[np2][1], wh2[np2][2], wh2[np2][3], whB + off);
                ldsm4(wl2[np2][0], wl2[np2][1], wl2[np2][2], wl2[np2][3], wlB + off);
            }
            #pragma unroll
            for (int mt = 0; mt < 4; ++mt)
                #pragma unroll
                for (int nt = 0; nt < 4; ++nt) {
                    const uint32_t bh0 = wh2[nt >> 1][(nt & 1) * 2];
                    const uint32_t bh1 = wh2[nt >> 1][(nt & 1) * 2 + 1];
                    const uint32_t bl0 = wl2[nt >> 1][(nt & 1) * 2];
                    const uint32_t bl1 = wl2[nt >> 1][(nt & 1) * 2 + 1];
                    mma16816(acc[mt][nt], ah[mt], bh0, bh1);
                    mma16816(acc[mt][nt], al[mt], bh0, bh1);
                    mma16816(acc[mt][nt], ah[mt], bl0, bl1);
                }
        }
    }
    #undef LOAD_CHUNK

    #pragma unroll
    for (int mt = 0; mt < 4; ++mt) {
        const int r0 = rowBase + wm * 64 + mt * 16 + (lane >> 2);
        #pragma unroll
        for (int nt = 0; nt < 4; ++nt) {
            const int c = colBase + wn * 32 + nt * 8 + (lane & 3) * 2;
            const float2 bv = *(const float2*)&bias[c];
            float vx0 = acc[mt][nt][0] + bv.x, vy0 = acc[mt][nt][1] + bv.y;
            float vx1 = acc[mt][nt][2] + bv.x, vy1 = acc[mt][nt][3] + bv.y;
            if (MODE == 0) {
                const int tsel = c / CDIM;
                const int rem  = c - tsel * CDIM;
                const int hh = rem >> 6, d = rem & 63;
                const int m0 = r0, b0 = m0 >> 11, n0 = m0 & 2047;
                const int n1 = n0 + 8;
                if (tsel == 0) { vx0 *= QSCALE; vy0 *= QSCALE; vx1 *= QSCALE; vy1 *= QSCALE; }
                __nv_bfloat16 h00 = bhi(vx0), h01 = bhi(vy0), h10 = bhi(vx1), h11 = bhi(vy1);
                __nv_bfloat16* dh = (tsel == 0) ? g_qhi : (tsel == 1) ? g_khi : g_vhi;
                __nv_bfloat16* dl = (tsel == 0) ? g_qlo : (tsel == 1) ? g_klo : g_vlo;
                const size_t i0 = (((size_t)b0 * HEADS + hh) * SEQ + n0) * DH + d;
                const size_t i1 = (((size_t)b0 * HEADS + hh) * SEQ + n1) * DH + d;
                *(__nv_bfloat162*)&dh[i0] = __nv_bfloat162(h00, h01);
                *(__nv_bfloat162*)&dl[i0] = __nv_bfloat162(blo(vx0, h00), blo(vy0, h01));
                *(__nv_bfloat162*)&dh[i1] = __nv_bfloat162(h10, h11);
                *(__nv_bfloat162*)&dl[i1] = __nv_bfloat162(blo(vx1, h10), blo(vy1, h11));
            } else {
                float2 v0, v1;
                v0.x = vx0; v0.y = vy0; v1.x = vx1; v1.y = vy1;
                *(float2*)&out[(size_t)r0 * CDIM + c] = v0;
                *(float2*)&out[(size_t)(r0 + 8) * CDIM + c] = v1;
            }
        }
    }
}

// ---------------------------------------------------------------------------
// HMMA flash attention v7: 128q x 64k tiles, 4 warps x 32 q-rows each.
// Each warp reads K/V tiles once but does 2x MMAs vs v5 -> smem-BW ratio
// drops below tensor demand. Q frags (2 m-tiles) register-resident.
// 72KB smem -> 2 CTAs/SM, __launch_bounds__(128,2) for ~230 regs headroom.
// ---------------------------------------------------------------------------
#define QLD 72
#define MSZ (64 * QLD)
#define BKHI 0
#define BKLO MSZ
#define BVHI (2 * MSZ)
#define BVLO (3 * MSZ)
#define BUFSZ (4 * MSZ)
#define ATTN_SMEM (2 * BUFSZ * 2)   // 73728 bytes

__global__ void __launch_bounds__(128, 2)
attn_kernel()
{
    extern __shared__ __nv_bfloat16 sm[];
    const uint32_t smb = smem_u32(sm);

    const int q0 = blockIdx.x * 128;
    const int h  = blockIdx.y;
    const int b  = blockIdx.z;
    const size_t base = ((size_t)(b * HEADS + h)) * SEQ * DH;

    const int tid  = threadIdx.x;
    const int lane = tid & 31;
    const int wrp  = tid >> 5;
    const int wq   = wrp * 32;          // warp's 32-row q slice

    const int a_r = lane & 15;
    const int a_k = (lane >> 4) * 8;
    const int b_r = (lane & 7) + ((lane >> 4) << 3);
    const int b_k = ((lane >> 3) & 1) * 8;
    const int v_k = (lane & 7) + (((lane >> 3) & 1) << 3);
    const int v_d = (lane >> 4) * 8;
    const int qr  = lane >> 2;
    const int qc  = (lane & 3) * 2;

    // ---- stage Q (128 rows, hi+lo) through buffer 0, extract fragments ----
    uint32_t qh[2][4][4], ql[2][4][4];
    {
        #pragma unroll
        for (int i = 0; i < 8; ++i) {
            const int idx = i * 128 + tid;      // 0..1023
            const int r = idx >> 3, c8 = idx & 7;
            *(uint4*)&sm[r * QLD + c8 * 8] =
                *(const uint4*)&g_qhi[base + (size_t)(q0 + r) * DH + c8 * 8];
            *(uint4*)&sm[2 * MSZ + r * QLD + c8 * 8] =
                *(const uint4*)&g_qlo[base + (size_t)(q0 + r) * DH + c8 * 8];
        }
        __syncthreads();
        #pragma unroll
        for (int mt = 0; mt < 2; ++mt)
            #pragma unroll
            for (int ks = 0; ks < 4; ++ks) {
                const uint32_t ro = (uint32_t)((wq + mt * 16 + a_r) * QLD + ks * 16 + a_k) * 2;
                ldsm4(qh[mt][ks][0], qh[mt][ks][1], qh[mt][ks][2], qh[mt][ks][3], smb + ro);
                ldsm4(ql[mt][ks][0], ql[mt][ks][1], ql[mt][ks][2], ql[mt][ks][3],
                      smb + (uint32_t)(2 * MSZ) * 2 + ro);
            }
        __syncthreads();   // Q reads done before cp.async overwrites buffer 0
    }

    #define LOAD_TILE(k0, buf)                                                        \
        do {                                                                          \
            const uint32_t _bb = smb + (uint32_t)((buf) * BUFSZ) * 2;                 \
            const __nv_bfloat16* _kh = g_khi + base + (size_t)(k0) * DH;              \
            const __nv_bfloat16* _kl = g_klo + base + (size_t)(k0) * DH;              \
            const __nv_bfloat16* _vh = g_vhi + base + (size_t)(k0) * DH;              \
            const __nv_bfloat16* _vl = g_vlo + base + (size_t)(k0) * DH;              \
            _Pragma("unroll")                                                         \
            for (int _i = 0; _i < 4; ++_i) {                                          \
                const int _idx = _i * 128 + tid;                                      \
                const int _r = _idx >> 3, _c = _idx & 7;                              \
                const uint32_t _so = (uint32_t)(_r * QLD + _c * 8) * 2;               \
                const size_t _go = (size_t)_r * 64 + _c * 8;                          \
                CP_ASYNC16(_bb + BKHI * 2 + _so, _kh + _go);                          \
                CP_ASYNC16(_bb + BKLO * 2 + _so, _kl + _go);                          \
                CP_ASYNC16(_bb + BVHI * 2 + _so, _vh + _go);                          \
                CP_ASYNC16(_bb + BVLO * 2 + _so, _vl + _go);                          \
            }                                                                         \
        } while (0)

    LOAD_TILE(0, 0);
    CP_COMMIT();

    float m_i[2][2] = {{-1e30f, -1e30f}, {-1e30f, -1e30f}};
    float l_i[2][2] = {{0.f, 0.f}, {0.f, 0.f}};
    float oacc[2][8][4] = {};

    for (int t = 0; t < 32; ++t) {
        const int buf = t & 1;
        __syncthreads();
        if (t < 31) {
            LOAD_TILE((t + 1) * 64, buf ^ 1);
            CP_COMMIT();
            CP_WAIT1();
        } else {
            CP_WAIT0();
        }
        __syncthreads();

        const uint32_t kh = smb + (uint32_t)(buf * BUFSZ + BKHI) * 2;
        const uint32_t kl = smb + (uint32_t)(buf * BUFSZ + BKLO) * 2;
        const uint32_t vh = smb + (uint32_t)(buf * BUFSZ + BVHI) * 2;
        const uint32_t vl = smb + (uint32_t)(buf * BUFSZ + BVLO) * 2;

        // ---- S = QK^T : 32q x 64k per warp, shared K fragments across mt ----
        float sacc[2][8][4] = {};
        #pragma unroll
        for (int ks = 0; ks < 4; ++ks) {
            #pragma unroll
            for (int ng = 0; ng < 4; ++ng) {
                uint32_t bf[4];
                ldsm4(bf[0], bf[1], bf[2], bf[3],
                      kh + (uint32_t)((ng * 16 + b_r) * QLD + ks * 16 + b_k) * 2);
                #pragma unroll
                for (int mt = 0; mt < 2; ++mt) {
                    mma16816(sacc[mt][ng * 2 + 0], qh[mt][ks], bf[0], bf[1]);
                    mma16816(sacc[mt][ng * 2 + 1], qh[mt][ks], bf[2], bf[3]);
                    mma16816(sacc[mt][ng * 2 + 0], ql[mt][ks], bf[0], bf[1]);
                    mma16816(sacc[mt][ng * 2 + 1], ql[mt][ks], bf[2], bf[3]);
                }
            }
        }
        #pragma unroll
        for (int ks = 0; ks < 4; ++ks) {
            #pragma unroll
            for (int ng = 0; ng < 4; ++ng) {
                uint32_t bf[4];
                ldsm4(bf[0], bf[1], bf[2], bf[3],
                      kl + (uint32_t)((ng * 16 + b_r) * QLD + ks * 16 + b_k) * 2);
                #pragma unroll
                for (int mt = 0; mt < 2; ++mt) {
                    mma16816(sacc[mt][ng * 2 + 0], qh[mt][ks], bf[0], bf[1]);
                    mma16816(sacc[mt][ng * 2 + 1], qh[mt][ks], bf[2], bf[3]);
                }
            }
        }

        // ---- online softmax (exp2 domain, warp-local, 4 rows per thread) ----
        #pragma unroll
        for (int mt = 0; mt < 2; ++mt)
            #pragma unroll
            for (int ri = 0; ri < 2; ++ri) {
                float mx = -1e30f;
                #pragma unroll
                for (int nt = 0; nt < 8; ++nt) {
                    mx = fmaxf(mx, sacc[mt][nt][ri * 2 + 0]);
                    mx = fmaxf(mx, sacc[mt][nt][ri * 2 + 1]);
                }
                mx = fmaxf(mx, __shfl_xor_sync(0xffffffffu, mx, 1));
                mx = fmaxf(mx, __shfl_xor_sync(0xffffffffu, mx, 2));
                const float mn = fmaxf(m_i[mt][ri], mx);
                const float alpha = ex2f(m_i[mt][ri] - mn);
                m_i[mt][ri] = mn;
                float r = 0.f;
                #pragma unroll
                for (int nt = 0; nt < 8; ++nt) {
                    float p0 = ex2f(sacc[mt][nt][ri * 2 + 0] - mn);
                    float p1 = ex2f(sacc[mt][nt][ri * 2 + 1] - mn);
                    sacc[mt][nt][ri * 2 + 0] = p0;
                    sacc[mt][nt][ri * 2 + 1] = p1;
                    r += p0 + p1;
                }
                r += __shfl_xor_sync(0xffffffffu, r, 1);
                r += __shfl_xor_sync(0xffffffffu, r, 2);
                l_i[mt][ri] = l_i[mt][ri] * alpha + r;
                #pragma unroll
                for (int nt = 0; nt < 8; ++nt) {
                    oacc[mt][nt][ri * 2 + 0] *= alpha;
                    oacc[mt][nt][ri * 2 + 1] *= alpha;
                }
            }

        // ---- PV: P frags from sacc, V frags shared across mt ----
        #pragma unroll
        for (int ks = 0; ks < 4; ++ks) {
            uint32_t ph[2][4], pl[2][4];
            #pragma unroll
            for (int mt = 0; mt < 2; ++mt) {
                const float s00 = sacc[mt][2 * ks][0],     s01 = sacc[mt][2 * ks][1];
                const float s02 = sacc[mt][2 * ks][2],     s03 = sacc[mt][2 * ks][3];
                const float s10 = sacc[mt][2 * ks + 1][0], s11 = sacc[mt][2 * ks + 1][1];
                const float s12 = sacc[mt][2 * ks + 1][2], s13 = sacc[mt][2 * ks + 1][3];
                ph[mt][0] = packbf(s00, s01);
                ph[mt][1] = packbf(s02, s03);
                ph[mt][2] = packbf(s10, s11);
                ph[mt][3] = packbf(s12, s13);
                pl[mt][0] = packbf(s00 - __uint_as_float(ph[mt][0] << 16),
                                   s01 - __uint_as_float(ph[mt][0] & 0xffff0000u));
                pl[mt][1] = packbf(s02 - __uint_as_float(ph[mt][1] << 16),
                                   s03 - __uint_as_float(ph[mt][1] & 0xffff0000u));
                pl[mt][2] = packbf(s10 - __uint_as_float(ph[mt][2] << 16),
                                   s11 - __uint_as_float(ph[mt][2] & 0xffff0000u));
                pl[mt][3] = packbf(s12 - __uint_as_float(ph[mt][3] << 16),
                                   s13 - __uint_as_float(ph[mt][3] & 0xffff0000u));
            }
            const uint32_t vrow = (uint32_t)((ks * 16 + v_k) * QLD) * 2;
            #pragma unroll
            for (int ng = 0; ng < 4; ++ng) {
                uint32_t bh[4], bl[4];
                const uint32_t voff = vrow + (uint32_t)(ng * 16 + v_d) * 2;
                ldsm4t(bh[0], bh[1], bh[2], bh[3], vh + voff);
                ldsm4t(bl[0], bl[1], bl[2], bl[3], vl + voff);
                #pragma unroll
                for (int mt = 0; mt < 2; ++mt) {
                    mma16816(oacc[mt][ng * 2 + 0], ph[mt], bh[0], bh[1]);
                    mma16816(oacc[mt][ng * 2 + 1], ph[mt], bh[2], bh[3]);
                    mma16816(oacc[mt][ng * 2 + 0], ph[mt], bl[0], bl[1]);
                    mma16816(oacc[mt][ng * 2 + 1], ph[mt], bl[2], bl[3]);
                    mma16816(oacc[mt][ng * 2 + 0], pl[mt], bh[0], bh[1]);
                    mma16816(oacc[mt][ng * 2 + 1], pl[mt], bh[2], bh[3]);
                }
            }
        }
    }

    // ---- epilogue: normalize, split hi/lo, write a_hi/a_lo [B,N,C] ----
    #pragma unroll
    for (int mt = 0; mt < 2; ++mt) {
        const float inv0 = 1.f / l_i[mt][0];
        const float inv1 = 1.f / l_i[mt][1];
        const int row0 = q0 + wq + mt * 16 + qr;
        #pragma unroll
        for (int nt = 0; nt < 8; ++nt) {
            const int col = h * DH + nt * 8 + qc;
            const size_t i0 = ((size_t)b * SEQ + row0) * CDIM + col;
            const size_t i1 = ((size_t)b * SEQ + row0 + 8) * CDIM + col;
            float o00 = oacc[mt][nt][0] * inv0, o01 = oacc[mt][nt][1] * inv0;
            float o10 = oacc[mt][nt][2] * inv1, o11 = oacc[mt][nt][3] * inv1;
            __nv_bfloat16 h00 = bhi(o00), h01 = bhi(o01), h10 = bhi(o10), h11 = bhi(o11);
            *(__nv_bfloat162*)&g_a_hi[i0] = __nv_bfloat162(h00, h01);
            *(__nv_bfloat162*)&g_a_lo[i0] = __nv_bfloat162(blo(o00, h00), blo(o01, h01));
            *(__nv_bfloat162*)&g_a_hi[i1] = __nv_bfloat162(h10, h11);
            *(__nv_bfloat162*)&g_a_lo[i1] = __nv_bfloat162(blo(o10, h10), blo(o11, h11));
        }
    }
    #undef LOAD_TILE
}

// ---------------------------------------------------------------------------
extern "C" void kernel_launch(void* const* d_in, const int* in_sizes, int n_in,
                              void* d_out, int out_size)
{
    const float* x      = (const float*)d_in[0];
    const float* qkv_w  = (const float*)d_in[1];
    const float* qkv_b  = (const float*)d_in[2];
    const float* proj_w = (const float*)d_in[3];
    const float* proj_b = (const float*)d_in[4];
    float* out = (float*)d_out;

    cudaFuncSetAttribute(mma_gemm<0>, cudaFuncAttributeMaxDynamicSharedMemorySize, GEMM_SMEM);
    cudaFuncSetAttribute(mma_gemm<1>, cudaFuncAttributeMaxDynamicSharedMemorySize, GEMM_SMEM);
    cudaFuncSetAttribute(attn_kernel, cudaFuncAttributeMaxDynamicSharedMemorySize, ATTN_SMEM);

    __nv_bfloat16 *a_hi, *a_lo, *w_hi, *w_lo, *w2_hi, *w2_lo;
    cudaGetSymbolAddress((void**)&a_hi, g_a_hi);
    cudaGetSymbolAddress((void**)&a_lo, g_a_lo);
    cudaGetSymbolAddress((void**)&w_hi, g_w_hi);
    cudaGetSymbolAddress((void**)&w_lo, g_w_lo);
    cudaGetSymbolAddress((void**)&w2_hi, g_w2_hi);
    cudaGetSymbolAddress((void**)&w2_lo, g_w2_lo);

    const int nx4 = MTOT * CDIM / 4;
    const int nw4 = 3 * CDIM * CDIM / 4;
    const int np4 = CDIM * CDIM / 4;

    // splits up front (proj_w into its own buffers, no dependency on attn)
    split_kernel<<<(nx4 + 255) / 256, 256>>>((const float4*)x,
        (__nv_bfloat162*)a_hi, (__nv_bfloat162*)a_lo, nx4);
    split_kernel<<<(nw4 + 255) / 256, 256>>>((const float4*)qkv_w,
        (__nv_bfloat162*)w_hi, (__nv_bfloat162*)w_lo, nw4);
    split_kernel<<<(np4 + 255) / 256, 256>>>((const float4*)proj_w,
        (__nv_bfloat162*)w2_hi, (__nv_bfloat162*)w2_lo, np4);

    mma_gemm<0><<<dim3(18, 64), 256, GEMM_SMEM>>>(a_hi, a_lo, w_hi, w_lo, qkv_b, nullptr);

    attn_kernel<<<dim3(SEQ / 128, HEADS, BATCH), 128, ATTN_SMEM>>>();

    mma_gemm<1><<<dim3(6, 64), 256, GEMM_SMEM>>>(a_hi, a_lo, w2_hi, w2_lo, proj_b, out);
}

// round 13
// speedup vs baseline: 1.0109x; 1.0109x over previous
#include <cuda_runtime.h>
#include <cuda_bf16.h>
#include <cstdint>

#define HEADS 12
#define SEQ   2048
#define BATCH 4
#define DH    64
#define CDIM  768
#define MTOT  8192   // BATCH*SEQ
#define NQKV ((size_t)BATCH * HEADS * SEQ * DH)

// ---------------- scratch (allocation-free) ----------------
__device__ __align__(16) __nv_bfloat16 g_qhi[NQKV], g_qlo[NQKV];
__device__ __align__(16) __nv_bfloat16 g_khi[NQKV], g_klo[NQKV];
__device__ __align__(16) __nv_bfloat16 g_vhi[NQKV], g_vlo[NQKV];
__device__ __align__(16) __nv_bfloat16 g_a_hi[(size_t)MTOT * CDIM];
__device__ __align__(16) __nv_bfloat16 g_a_lo[(size_t)MTOT * CDIM];
__device__ __align__(16) __nv_bfloat16 g_w_hi[(size_t)3 * CDIM * CDIM];
__device__ __align__(16) __nv_bfloat16 g_w_lo[(size_t)3 * CDIM * CDIM];
__device__ __align__(16) __nv_bfloat16 g_w2_hi[(size_t)CDIM * CDIM];
__device__ __align__(16) __nv_bfloat16 g_w2_lo[(size_t)CDIM * CDIM];

// Q prescale: 1/sqrt(64) * log2(e)
#define QSCALE 0.1803368801111204f

// ---------------- helpers ----------------
__device__ __forceinline__ uint32_t smem_u32(const void* p) {
    uint32_t a;
    asm("{ .reg .u64 t; cvta.to.shared.u64 t, %1; cvt.u32.u64 %0, t; }" : "=r"(a) : "l"(p));
    return a;
}
__device__ __forceinline__ void ldsm4(uint32_t& r0, uint32_t& r1, uint32_t& r2, uint32_t& r3,
                                      uint32_t addr) {
    asm volatile("ldmatrix.sync.aligned.m8n8.x4.shared.b16 {%0,%1,%2,%3}, [%4];"
                 : "=r"(r0), "=r"(r1), "=r"(r2), "=r"(r3) : "r"(addr));
}
__device__ __forceinline__ void ldsm4t(uint32_t& r0, uint32_t& r1, uint32_t& r2, uint32_t& r3,
                                       uint32_t addr) {
    asm volatile("ldmatrix.sync.aligned.m8n8.x4.trans.shared.b16 {%0,%1,%2,%3}, [%4];"
                 : "=r"(r0), "=r"(r1), "=r"(r2), "=r"(r3) : "r"(addr));
}
__device__ __forceinline__ void mma16816(float* c, const uint32_t* a, uint32_t b0, uint32_t b1) {
    asm volatile("mma.sync.aligned.m16n8k16.row.col.f32.bf16.bf16.f32 "
                 "{%0,%1,%2,%3}, {%4,%5,%6,%7}, {%8,%9}, {%0,%1,%2,%3};"
                 : "+f"(c[0]), "+f"(c[1]), "+f"(c[2]), "+f"(c[3])
                 : "r"(a[0]), "r"(a[1]), "r"(a[2]), "r"(a[3]), "r"(b0), "r"(b1));
}
__device__ __forceinline__ __nv_bfloat16 bhi(float x) { return __float2bfloat16(x); }
__device__ __forceinline__ __nv_bfloat16 blo(float x, __nv_bfloat16 h) {
    return __float2bfloat16(x - __bfloat162float(h));
}
__device__ __forceinline__ float ex2f(float x) {
    float y;
    asm("ex2.approx.f32 %0, %1;" : "=f"(y) : "f"(x));
    return y;
}
__device__ __forceinline__ uint32_t packbf(float lo_, float hi_) {
    uint32_t r;
    asm("cvt.rn.bf16x2.f32 %0, %1, %2;" : "=r"(r) : "f"(hi_), "f"(lo_));
    return r;
}

#define CP_ASYNC16(dst, src) \
    asm volatile("cp.async.cg.shared.global [%0], [%1], 16;" :: "r"(dst), "l"(src))
#define CP_COMMIT() asm volatile("cp.async.commit_group;")
#define CP_WAIT1()  asm volatile("cp.async.wait_group 1;")
#define CP_WAIT0()  asm volatile("cp.async.wait_group 0;")

// ---------------------------------------------------------------------------
__global__ void split_kernel(const float4* __restrict__ src,
                             __nv_bfloat162* __restrict__ hi,
                             __nv_bfloat162* __restrict__ lo, int n4)
{
    int i = blockIdx.x * 256 + threadIdx.x;
    if (i < n4) {
        float4 v = src[i];
        __nv_bfloat16 hx = __float2bfloat16(v.x);
        __nv_bfloat16 hy = __float2bfloat16(v.y);
        __nv_bfloat16 hz = __float2bfloat16(v.z);
        __nv_bfloat16 hw = __float2bfloat16(v.w);
        hi[2 * i]     = __nv_bfloat162(hx, hy);
        hi[2 * i + 1] = __nv_bfloat162(hz, hw);
        lo[2 * i]     = __nv_bfloat162(blo(v.x, hx), blo(v.y, hy));
        lo[2 * i + 1] = __nv_bfloat162(blo(v.z, hz), blo(v.w, hw));
    }
}

// ---------------------------------------------------------------------------
// HMMA bf16x3 GEMM v3: single K sweep; the 3 error-comp products issued as
// SEPARATE full (mt,nt) passes so each accumulator's successive MMAs are
// spaced by 15 independent ones (kills tensor-pipe dependency bubbles).
// ---------------------------------------------------------------------------
#define LDT2 40
#define GM_MSZ (128 * LDT2)
#define GAHI 0
#define GALO GM_MSZ
#define GWHI (2 * GM_MSZ)
#define GWLO (3 * GM_MSZ)
#define GM_BUF (4 * GM_MSZ)
#define GEMM_SMEM (2 * GM_BUF * 2)     // 81920 bytes
#define NCHUNK 24

template <int MODE>
__global__ void __launch_bounds__(256, 2)
mma_gemm(const __nv_bfloat16* __restrict__ a_hi, const __nv_bfloat16* __restrict__ a_lo,
         const __nv_bfloat16* __restrict__ w_hi, const __nv_bfloat16* __restrict__ w_lo,
         const float* __restrict__ bias, float* __restrict__ out)
{
    extern __shared__ __nv_bfloat16 sm[];
    const uint32_t smb = smem_u32(sm);
    const int tid  = threadIdx.x;
    const int lane = tid & 31;
    const int wrp  = tid >> 5;
    const int wm   = wrp & 1;
    const int wn   = wrp >> 1;
    const int rowBase = blockIdx.y * 128;
    const int colBase = blockIdx.x * 128;

    const int a_r = lane & 15;
    const int a_k = (lane >> 4) * 8;
    const int b_r = (lane & 7) + ((lane >> 4) << 3);
    const int b_k = ((lane >> 3) & 1) * 8;

    float acc[4][4][4] = {};

    #define LOAD_CHUNK(kk, buf)                                                       \
        do {                                                                          \
            const uint32_t _bb = smb + (uint32_t)((buf) * GM_BUF) * 2;                \
            _Pragma("unroll")                                                         \
            for (int _i = 0; _i < 2; ++_i) {                                          \
                const int _idx = _i * 256 + tid;                                      \
                const int _r = _idx >> 2, _c = _idx & 3;                              \
                const size_t _ga = (size_t)(rowBase + _r) * CDIM + (kk) + _c * 8;     \
                const size_t _gw = (size_t)(colBase + _r) * CDIM + (kk) + _c * 8;     \
                const uint32_t _so = (uint32_t)(_r * LDT2 + _c * 8) * 2;              \
                CP_ASYNC16(_bb + GAHI * 2 + _so, a_hi + _ga);                         \
                CP_ASYNC16(_bb + GALO * 2 + _so, a_lo + _ga);                         \
                CP_ASYNC16(_bb + GWHI * 2 + _so, w_hi + _gw);                         \
                CP_ASYNC16(_bb + GWLO * 2 + _so, w_lo + _gw);                         \
            }                                                                         \
        } while (0)

    LOAD_CHUNK(0, 0);
    CP_COMMIT();

    for (int t = 0; t < NCHUNK; ++t) {
        const int buf = t & 1;
        __syncthreads();
        if (t < NCHUNK - 1) {
            LOAD_CHUNK((t + 1) * 32, buf ^ 1);
            CP_COMMIT();
            CP_WAIT1();
        } else {
            CP_WAIT0();
        }
        __syncthreads();

        const uint32_t ahB = smb + (uint32_t)(buf * GM_BUF + GAHI) * 2;
        const uint32_t alB = smb + (uint32_t)(buf * GM_BUF + GALO) * 2;
        const uint32_t whB = smb + (uint32_t)(buf * GM_BUF + GWHI) * 2;
        const uint32_t wlB = smb + (uint32_t)(buf * GM_BUF + GWLO) * 2;

        #pragma unroll
        for (int ks = 0; ks < 2; ++ks) {
            uint32_t ah[4][4], al[4][4], wh2[2][4], wl2[2][4];
            #pragma unroll
            for (int mt = 0; mt < 4; ++mt) {
                const uint32_t off =
                    (uint32_t)((wm * 64 + mt * 16 + a_r) * LDT2 + ks * 16 + a_k) * 2;
                ldsm4(ah[mt][0], ah[mt][1], ah[mt][2], ah[mt][3], ahB + off);
                ldsm4(al[mt][0], al[mt][1], al[mt][2], al[mt][3], alB + off);
            }
            #pragma unroll
            for (int np2 = 0; np2 < 2; ++np2) {
                const uint32_t off =
                    (uint32_t)((wn * 32 + np2 * 16 + b_r) * LDT2 + ks * 16 + b_k) * 2;
                ldsm4(wh2[np2][0], wh2[np2][1], wh2[np2][2], wh2[np2][3], whB + off);
                ldsm4(wl2[np2][0], wl2[np2][1], wl2[np2][2], wl2[np2][3], wlB + off);
            }
            // pass 0: ah * wh   (16 independent accumulators back-to-back)
            #pragma unroll
            for (int mt = 0; mt < 4; ++mt)
                #pragma unroll
                for (int nt = 0; nt < 4; ++nt)
                    mma16816(acc[mt][nt], ah[mt],
                             wh2[nt >> 1][(nt & 1) * 2], wh2[nt >> 1][(nt & 1) * 2 + 1]);
            // pass 1: al * wh
            #pragma unroll
            for (int mt = 0; mt < 4; ++mt)
                #pragma unroll
                for (int nt = 0; nt < 4; ++nt)
                    mma16816(acc[mt][nt], al[mt],
                             wh2[nt >> 1][(nt & 1) * 2], wh2[nt >> 1][(nt & 1) * 2 + 1]);
            // pass 2: ah * wl
            #pragma unroll
            for (int mt = 0; mt < 4; ++mt)
                #pragma unroll
                for (int nt = 0; nt < 4; ++nt)
                    mma16816(acc[mt][nt], ah[mt],
                             wl2[nt >> 1][(nt & 1) * 2], wl2[nt >> 1][(nt & 1) * 2 + 1]);
        }
    }
    #undef LOAD_CHUNK

    #pragma unroll
    for (int mt = 0; mt < 4; ++mt) {
        const int r0 = rowBase + wm * 64 + mt * 16 + (lane >> 2);
        #pragma unroll
        for (int nt = 0; nt < 4; ++nt) {
            const int c = colBase + wn * 32 + nt * 8 + (lane & 3) * 2;
            const float2 bv = *(const float2*)&bias[c];
            float vx0 = acc[mt][nt][0] + bv.x, vy0 = acc[mt][nt][1] + bv.y;
            float vx1 = acc[mt][nt][2] + bv.x, vy1 = acc[mt][nt][3] + bv.y;
            if (MODE == 0) {
                const int tsel = c / CDIM;
                const int rem  = c - tsel * CDIM;
                const int hh = rem >> 6, d = rem & 63;
                const int m0 = r0, b0 = m0 >> 11, n0 = m0 & 2047;
                const int n1 = n0 + 8;
                if (tsel == 0) { vx0 *= QSCALE; vy0 *= QSCALE; vx1 *= QSCALE; vy1 *= QSCALE; }
                __nv_bfloat16 h00 = bhi(vx0), h01 = bhi(vy0), h10 = bhi(vx1), h11 = bhi(vy1);
                __nv_bfloat16* dh = (tsel == 0) ? g_qhi : (tsel == 1) ? g_khi : g_vhi;
                __nv_bfloat16* dl = (tsel == 0) ? g_qlo : (tsel == 1) ? g_klo : g_vlo;
                const size_t i0 = (((size_t)b0 * HEADS + hh) * SEQ + n0) * DH + d;
                const size_t i1 = (((size_t)b0 * HEADS + hh) * SEQ + n1) * DH + d;
                *(__nv_bfloat162*)&dh[i0] = __nv_bfloat162(h00, h01);
                *(__nv_bfloat162*)&dl[i0] = __nv_bfloat162(blo(vx0, h00), blo(vy0, h01));
                *(__nv_bfloat162*)&dh[i1] = __nv_bfloat162(h10, h11);
                *(__nv_bfloat162*)&dl[i1] = __nv_bfloat162(blo(vx1, h10), blo(vy1, h11));
            } else {
                float2 v0, v1;
                v0.x = vx0; v0.y = vy0; v1.x = vx1; v1.y = vy1;
                *(float2*)&out[(size_t)r0 * CDIM + c] = v0;
                *(float2*)&out[(size_t)(r0 + 8) * CDIM + c] = v1;
            }
        }
    }
}

// ---------------------------------------------------------------------------
// HMMA flash attention v5 (round-10 best, verbatim): 64q x 64k tiles,
// 128 threads, Q frags register-resident, P frags direct from S accumulators,
// V row-major with ldmatrix.trans. 72KB smem -> 3 CTAs/SM.
// ---------------------------------------------------------------------------
#define QLD 72
#define MSZ (64 * QLD)
#define BKHI 0
#define BKLO MSZ
#define BVHI (2 * MSZ)
#define BVLO (3 * MSZ)
#define BUFSZ (4 * MSZ)
#define ATTN_SMEM (2 * BUFSZ * 2)   // 73728 bytes

__global__ void __launch_bounds__(128, 3)
attn_kernel()
{
    extern __shared__ __nv_bfloat16 sm[];
    const uint32_t smb = smem_u32(sm);

    const int q0 = blockIdx.x * 64;
    const int h  = blockIdx.y;
    const int b  = blockIdx.z;
    const size_t base = ((size_t)(b * HEADS + h)) * SEQ * DH;

    const int tid  = threadIdx.x;
    const int lane = tid & 31;
    const int wrp  = tid >> 5;
    const int wq   = wrp * 16;

    const int a_r = lane & 15;
    const int a_k = (lane >> 4) * 8;
    const int b_r = (lane & 7) + ((lane >> 4) << 3);
    const int b_k = ((lane >> 3) & 1) * 8;
    const int v_k = (lane & 7) + (((lane >> 3) & 1) << 3);
    const int v_d = (lane >> 4) * 8;
    const int qr  = lane >> 2;
    const int qc  = (lane & 3) * 2;

    uint32_t qh[4][4], ql[4][4];
    {
        #pragma unroll
        for (int i = 0; i < 4; ++i) {
            const int idx = i * 128 + tid;
            const int r = idx >> 3, c8 = idx & 7;
            *(uint4*)&sm[r * QLD + c8 * 8] =
                *(const uint4*)&g_qhi[base + (size_t)(q0 + r) * DH + c8 * 8];
            *(uint4*)&sm[MSZ + r * QLD + c8 * 8] =
                *(const uint4*)&g_qlo[base + (size_t)(q0 + r) * DH + c8 * 8];
        }
        __syncthreads();
        #pragma unroll
        for (int ks = 0; ks < 4; ++ks) {
            ldsm4(qh[ks][0], qh[ks][1], qh[ks][2], qh[ks][3],
                  smb + (uint32_t)((wq + a_r) * QLD + ks * 16 + a_k) * 2);
            ldsm4(ql[ks][0], ql[ks][1], ql[ks][2], ql[ks][3],
                  smb + (uint32_t)(MSZ + (wq + a_r) * QLD + ks * 16 + a_k) * 2);
        }
        __syncthreads();
    }

    #define LOAD_TILE(k0, buf)                                                        \
        do {                                                                          \
            const uint32_t _bb = smb + (uint32_t)((buf) * BUFSZ) * 2;                 \
            const __nv_bfloat16* _kh = g_khi + base + (size_t)(k0) * DH;              \
            const __nv_bfloat16* _kl = g_klo + base + (size_t)(k0) * DH;              \
            const __nv_bfloat16* _vh = g_vhi + base + (size_t)(k0) * DH;              \
            const __nv_bfloat16* _vl = g_vlo + base + (size_t)(k0) * DH;              \
            _Pragma("unroll")                                                         \
            for (int _i = 0; _i < 4; ++_i) {                                          \
                const int _idx = _i * 128 + tid;                                      \
                const int _r = _idx >> 3, _c = _idx & 7;                              \
                const uint32_t _so = (uint32_t)(_r * QLD + _c * 8) * 2;               \
                const size_t _go = (size_t)_r * 64 + _c * 8;                          \
                CP_ASYNC16(_bb + BKHI * 2 + _so, _kh + _go);                          \
                CP_ASYNC16(_bb + BKLO * 2 + _so, _kl + _go);                          \
                CP_ASYNC16(_bb + BVHI * 2 + _so, _vh + _go);                          \
                CP_ASYNC16(_bb + BVLO * 2 + _so, _vl + _go);                          \
            }                                                                         \
        } while (0)

    LOAD_TILE(0, 0);
    CP_COMMIT();

    float m_i[2] = {-1e30f, -1e30f};
    float l_i[2] = {0.f, 0.f};
    float oacc[8][4] = {};

    for (int t = 0; t < 32; ++t) {
        const int buf = t & 1;
        __syncthreads();
        if (t < 31) {
            LOAD_TILE((t + 1) * 64, buf ^ 1);
            CP_COMMIT();
            CP_WAIT1();
        } else {
            CP_WAIT0();
        }
        __syncthreads();

        const uint32_t kh = smb + (uint32_t)(buf * BUFSZ + BKHI) * 2;
        const uint32_t kl = smb + (uint32_t)(buf * BUFSZ + BKLO) * 2;
        const uint32_t vh = smb + (uint32_t)(buf * BUFSZ + BVHI) * 2;
        const uint32_t vl = smb + (uint32_t)(buf * BUFSZ + BVLO) * 2;

        // ---- S = QK^T ----
        float sacc[8][4] = {};
        #pragma unroll
        for (int ks = 0; ks < 4; ++ks) {
            #pragma unroll
            for (int ng = 0; ng < 4; ++ng) {
                uint32_t bf[4];
                ldsm4(bf[0], bf[1], bf[2], bf[3],
                      kh + (uint32_t)((ng * 16 + b_r) * QLD + ks * 16 + b_k) * 2);
                mma16816(sacc[ng * 2 + 0], qh[ks], bf[0], bf[1]);
                mma16816(sacc[ng * 2 + 1], qh[ks], bf[2], bf[3]);
                mma16816(sacc[ng * 2 + 0], ql[ks], bf[0], bf[1]);
                mma16816(sacc[ng * 2 + 1], ql[ks], bf[2], bf[3]);
            }
        }
        #pragma unroll
        for (int ks = 0; ks < 4; ++ks) {
            #pragma unroll
            for (int ng = 0; ng < 4; ++ng) {
                uint32_t bf[4];
                ldsm4(bf[0], bf[1], bf[2], bf[3],
                      kl + (uint32_t)((ng * 16 + b_r) * QLD + ks * 16 + b_k) * 2);
                mma16816(sacc[ng * 2 + 0], qh[ks], bf[0], bf[1]);
                mma16816(sacc[ng * 2 + 1], qh[ks], bf[2], bf[3]);
            }
        }

        // ---- online softmax (exp2 domain, warp-local rows qr, qr+8) ----
        #pragma unroll
        for (int ri = 0; ri < 2; ++ri) {
            float mx = -1e30f;
            #pragma unroll
            for (int nt = 0; nt < 8; ++nt) {
                mx = fmaxf(mx, sacc[nt][ri * 2 + 0]);
                mx = fmaxf(mx, sacc[nt][ri * 2 + 1]);
            }
            mx = fmaxf(mx, __shfl_xor_sync(0xffffffffu, mx, 1));
            mx = fmaxf(mx, __shfl_xor_sync(0xffffffffu, mx, 2));
            const float mn = fmaxf(m_i[ri], mx);
            const float alpha = ex2f(m_i[ri] - mn);
            m_i[ri] = mn;
            float r = 0.f;
            #pragma unroll
            for (int nt = 0; nt < 8; ++nt) {
                float p0 = ex2f(sacc[nt][ri * 2 + 0] - mn);
                float p1 = ex2f(sacc[nt][ri * 2 + 1] - mn);
                sacc[nt][ri * 2 + 0] = p0;
                sacc[nt][ri * 2 + 1] = p1;
                r += p0 + p1;
            }
            r += __shfl_xor_sync(0xffffffffu, r, 1);
            r += __shfl_xor_sync(0xffffffffu, r, 2);
            l_i[ri] = l_i[ri] * alpha + r;
            #pragma unroll
            for (int nt = 0; nt < 8; ++nt) {
                oacc[nt][ri * 2 + 0] *= alpha;
                oacc[nt][ri * 2 + 1] *= alpha;
            }
        }

        // ---- PV: P frags from sacc, V frags via ldmatrix.trans ----
        #pragma unroll
        for (int ks = 0; ks < 4; ++ks) {
            uint32_t ph[4], pl[4];
            {
                const float s00 = sacc[2 * ks][0],     s01 = sacc[2 * ks][1];
                const float s02 = sacc[2 * ks][2],     s03 = sacc[2 * ks][3];
                const float s10 = sacc[2 * ks + 1][0], s11 = sacc[2 * ks + 1][1];
                const float s12 = sacc[2 * ks + 1][2], s13 = sacc[2 * ks + 1][3];
                ph[0] = packbf(s00, s01);
                ph[1] = packbf(s02, s03);
                ph[2] = packbf(s10, s11);
                ph[3] = packbf(s12, s13);
                pl[0] = packbf(s00 - __uint_as_float(ph[0] << 16),
                               s01 - __uint_as_float(ph[0] & 0xffff0000u));
                pl[1] = packbf(s02 - __uint_as_float(ph[1] << 16),
                               s03 - __uint_as_float(ph[1] & 0xffff0000u));
                pl[2] = packbf(s10 - __uint_as_float(ph[2] << 16),
                               s11 - __uint_as_float(ph[2] & 0xffff0000u));
                pl[3] = packbf(s12 - __uint_as_float(ph[3] << 16),
                               s13 - __uint_as_float(ph[3] & 0xffff0000u));
            }
            const uint32_t vrow = (uint32_t)((ks * 16 + v_k) * QLD) * 2;
            #pragma unroll
            for (int ng = 0; ng < 4; ++ng) {
                uint32_t bh[4], bl[4];
                const uint32_t voff = vrow + (uint32_t)(ng * 16 + v_d) * 2;
                ldsm4t(bh[0], bh[1], bh[2], bh[3], vh + voff);
                ldsm4t(bl[0], bl[1], bl[2], bl[3], vl + voff);
                mma16816(oacc[ng * 2 + 0], ph, bh[0], bh[1]);
                mma16816(oacc[ng * 2 + 1], ph, bh[2], bh[3]);
                mma16816(oacc[ng * 2 + 0], ph, bl[0], bl[1]);
                mma16816(oacc[ng * 2 + 1], ph, bl[2], bl[3]);
                mma16816(oacc[ng * 2 + 0], pl, bh[0], bh[1]);
                mma16816(oacc[ng * 2 + 1], pl, bh[2], bh[3]);
            }
        }
    }

    // ---- epilogue: normalize, split hi/lo, write a_hi/a_lo [B,N,C] ----
    const float inv0 = 1.f / l_i[0];
    const float inv1 = 1.f / l_i[1];
    const int row0 = q0 + wq + qr;
    #pragma unroll
    for (int nt = 0; nt < 8; ++nt) {
        const int col = h * DH + nt * 8 + qc;
        const size_t i0 = ((size_t)b * SEQ + row0) * CDIM + col;
        const size_t i1 = ((size_t)b * SEQ + row0 + 8) * CDIM + col;
        float o00 = oacc[nt][0] * inv0, o01 = oacc[nt][1] * inv0;
        float o10 = oacc[nt][2] * inv1, o11 = oacc[nt][3] * inv1;
        __nv_bfloat16 h00 = bhi(o00), h01 = bhi(o01), h10 = bhi(o10), h11 = bhi(o11);
        *(__nv_bfloat162*)&g_a_hi[i0] = __nv_bfloat162(h00, h01);
        *(__nv_bfloat162*)&g_a_lo[i0] = __nv_bfloat162(blo(o00, h00), blo(o01, h01));
        *(__nv_bfloat162*)&g_a_hi[i1] = __nv_bfloat162(h10, h11);
        *(__nv_bfloat162*)&g_a_lo[i1] = __nv_bfloat162(blo(o10, h10), blo(o11, h11));
    }
    #undef LOAD_TILE
}

// ---------------------------------------------------------------------------
extern "C" void kernel_launch(void* const* d_in, const int* in_sizes, int n_in,
                              void* d_out, int out_size)
{
    const float* x      = (const float*)d_in[0];
    const float* qkv_w  = (const float*)d_in[1];
    const float* qkv_b  = (const float*)d_in[2];
    const float* proj_w = (const float*)d_in[3];
    const float* proj_b = (const float*)d_in[4];
    float* out = (float*)d_out;

    cudaFuncSetAttribute(mma_gemm<0>, cudaFuncAttributeMaxDynamicSharedMemorySize, GEMM_SMEM);
    cudaFuncSetAttribute(mma_gemm<1>, cudaFuncAttributeMaxDynamicSharedMemorySize, GEMM_SMEM);
    cudaFuncSetAttribute(attn_kernel, cudaFuncAttributeMaxDynamicSharedMemorySize, ATTN_SMEM);

    __nv_bfloat16 *a_hi, *a_lo, *w_hi, *w_lo, *w2_hi, *w2_lo;
    cudaGetSymbolAddress((void**)&a_hi, g_a_hi);
    cudaGetSymbolAddress((void**)&a_lo, g_a_lo);
    cudaGetSymbolAddress((void**)&w_hi, g_w_hi);
    cudaGetSymbolAddress((void**)&w_lo, g_w_lo);
    cudaGetSymbolAddress((void**)&w2_hi, g_w2_hi);
    cudaGetSymbolAddress((void**)&w2_lo, g_w2_lo);

    const int nx4 = MTOT * CDIM / 4;
    const int nw4 = 3 * CDIM * CDIM / 4;
    const int np4 = CDIM * CDIM / 4;

    // splits up front (proj_w into separate buffers; no post-attn split)
    split_kernel<<<(nx4 + 255) / 256, 256>>>((const float4*)x,
        (__nv_bfloat162*)a_hi, (__nv_bfloat162*)a_lo, nx4);
    split_kernel<<<(nw4 + 255) / 256, 256>>>((const float4*)qkv_w,
        (__nv_bfloat162*)w_hi, (__nv_bfloat162*)w_lo, nw4);
    split_kernel<<<(np4 + 255) / 256, 256>>>((const float4*)proj_w,
        (__nv_bfloat162*)w2_hi, (__nv_bfloat162*)w2_lo, np4);

    mma_gemm<0><<<dim3(18, 64), 256, GEMM_SMEM>>>(a_hi, a_lo, w_hi, w_lo, qkv_b, nullptr);

    attn_kernel<<<dim3(SEQ / 64, HEADS, BATCH), 128, ATTN_SMEM>>>();

    mma_gemm<1><<<dim3(6, 64), 256, GEMM_SMEM>>>(a_hi, a_lo, w2_hi, w2_lo, proj_b, out);
}

// round 14
// speedup vs baseline: 1.0113x; 1.0004x over previous
#include <cuda_runtime.h>
#include <cuda_bf16.h>
#include <cstdint>

#define HEADS 12
#define SEQ   2048
#define BATCH 4
#define DH    64
#define CDIM  768
#define MTOT  8192   // BATCH*SEQ
#define NQKV ((size_t)BATCH * HEADS * SEQ * DH)

// ---------------- scratch (allocation-free) ----------------
__device__ __align__(16) __nv_bfloat16 g_qhi[NQKV], g_qlo[NQKV];
__device__ __align__(16) __nv_bfloat16 g_khi[NQKV], g_klo[NQKV];
__device__ __align__(16) __nv_bfloat16 g_vhi[NQKV], g_vlo[NQKV];
__device__ __align__(16) __nv_bfloat16 g_a_hi[(size_t)MTOT * CDIM];
__device__ __align__(16) __nv_bfloat16 g_a_lo[(size_t)MTOT * CDIM];
__device__ __align__(16) __nv_bfloat16 g_w_hi[(size_t)3 * CDIM * CDIM];
__device__ __align__(16) __nv_bfloat16 g_w_lo[(size_t)3 * CDIM * CDIM];
__device__ __align__(16) __nv_bfloat16 g_w2_hi[(size_t)CDIM * CDIM];
__device__ __align__(16) __nv_bfloat16 g_w2_lo[(size_t)CDIM * CDIM];

// Q prescale: 1/sqrt(64) * log2(e)
#define QSCALE 0.1803368801111204f

// ---------------- helpers ----------------
__device__ __forceinline__ uint32_t smem_u32(const void* p) {
    uint32_t a;
    asm("{ .reg .u64 t; cvta.to.shared.u64 t, %1; cvt.u32.u64 %0, t; }" : "=r"(a) : "l"(p));
    return a;
}
__device__ __forceinline__ void ldsm4(uint32_t& r0, uint32_t& r1, uint32_t& r2, uint32_t& r3,
                                      uint32_t addr) {
    asm volatile("ldmatrix.sync.aligned.m8n8.x4.shared.b16 {%0,%1,%2,%3}, [%4];"
                 : "=r"(r0), "=r"(r1), "=r"(r2), "=r"(r3) : "r"(addr));
}
__device__ __forceinline__ void ldsm4t(uint32_t& r0, uint32_t& r1, uint32_t& r2, uint32_t& r3,
                                       uint32_t addr) {
    asm volatile("ldmatrix.sync.aligned.m8n8.x4.trans.shared.b16 {%0,%1,%2,%3}, [%4];"
                 : "=r"(r0), "=r"(r1), "=r"(r2), "=r"(r3) : "r"(addr));
}
__device__ __forceinline__ void mma16816(float* c, const uint32_t* a, uint32_t b0, uint32_t b1) {
    asm volatile("mma.sync.aligned.m16n8k16.row.col.f32.bf16.bf16.f32 "
                 "{%0,%1,%2,%3}, {%4,%5,%6,%7}, {%8,%9}, {%0,%1,%2,%3};"
                 : "+f"(c[0]), "+f"(c[1]), "+f"(c[2]), "+f"(c[3])
                 : "r"(a[0]), "r"(a[1]), "r"(a[2]), "r"(a[3]), "r"(b0), "r"(b1));
}
__device__ __forceinline__ __nv_bfloat16 bhi(float x) { return __float2bfloat16(x); }
__device__ __forceinline__ __nv_bfloat16 blo(float x, __nv_bfloat16 h) {
    return __float2bfloat16(x - __bfloat162float(h));
}
__device__ __forceinline__ float ex2f(float x) {
    float y;
    asm("ex2.approx.f32 %0, %1;" : "=f"(y) : "f"(x));
    return y;
}
__device__ __forceinline__ uint32_t packbf(float lo_, float hi_) {
    uint32_t r;
    asm("cvt.rn.bf16x2.f32 %0, %1, %2;" : "=r"(r) : "f"(hi_), "f"(lo_));
    return r;
}

#define CP_ASYNC16(dst, src) \
    asm volatile("cp.async.cg.shared.global [%0], [%1], 16;" :: "r"(dst), "l"(src))
#define CP_COMMIT() asm volatile("cp.async.commit_group;")
#define CP_WAIT0()  asm volatile("cp.async.wait_group 0;")

// ---------------------------------------------------------------------------
__global__ void split_kernel(const float4* __restrict__ src,
                             __nv_bfloat162* __restrict__ hi,
                             __nv_bfloat162* __restrict__ lo, int n4)
{
    int i = blockIdx.x * 256 + threadIdx.x;
    if (i < n4) {
        float4 v = src[i];
        __nv_bfloat16 hx = __float2bfloat16(v.x);
        __nv_bfloat16 hy = __float2bfloat16(v.y);
        __nv_bfloat16 hz = __float2bfloat16(v.z);
        __nv_bfloat16 hw = __float2bfloat16(v.w);
        hi[2 * i]     = __nv_bfloat162(hx, hy);
        hi[2 * i + 1] = __nv_bfloat162(hz, hw);
        lo[2 * i]     = __nv_bfloat162(blo(v.x, hx), blo(v.y, hy));
        lo[2 * i + 1] = __nv_bfloat162(blo(v.z, hz), blo(v.w, hw));
    }
}

// ---------------------------------------------------------------------------
// HMMA bf16x3 GEMM v4: single-sync cp.async pipeline (1 barrier per chunk).
// ---------------------------------------------------------------------------
#define LDT2 40
#define GM_MSZ (128 * LDT2)
#define GAHI 0
#define GALO GM_MSZ
#define GWHI (2 * GM_MSZ)
#define GWLO (3 * GM_MSZ)
#define GM_BUF (4 * GM_MSZ)
#define GEMM_SMEM (2 * GM_BUF * 2)     // 81920 bytes
#define NCHUNK 24

template <int MODE>
__global__ void __launch_bounds__(256, 2)
mma_gemm(const __nv_bfloat16* __restrict__ a_hi, const __nv_bfloat16* __restrict__ a_lo,
         const __nv_bfloat16* __restrict__ w_hi, const __nv_bfloat16* __restrict__ w_lo,
         const float* __restrict__ bias, float* __restrict__ out)
{
    extern __shared__ __nv_bfloat16 sm[];
    const uint32_t smb = smem_u32(sm);
    const int tid  = threadIdx.x;
    const int lane = tid & 31;
    const int wrp  = tid >> 5;
    const int wm   = wrp & 1;
    const int wn   = wrp >> 1;
    const int rowBase = blockIdx.y * 128;
    const int colBase = blockIdx.x * 128;

    const int a_r = lane & 15;
    const int a_k = (lane >> 4) * 8;
    const int b_r = (lane & 7) + ((lane >> 4) << 3);
    const int b_k = ((lane >> 3) & 1) * 8;

    float acc[4][4][4] = {};

    #define LOAD_CHUNK(kk, buf)                                                       \
        do {                                                                          \
            const uint32_t _bb = smb + (uint32_t)((buf) * GM_BUF) * 2;                \
            _Pragma("unroll")                                                         \
            for (int _i = 0; _i < 2; ++_i) {                                          \
                const int _idx = _i * 256 + tid;                                      \
                const int _r = _idx >> 2, _c = _idx & 3;                              \
                const size_t _ga = (size_t)(rowBase + _r) * CDIM + (kk) + _c * 8;     \
                const size_t _gw = (size_t)(colBase + _r) * CDIM + (kk) + _c * 8;     \
                const uint32_t _so = (uint32_t)(_r * LDT2 + _c * 8) * 2;              \
                CP_ASYNC16(_bb + GAHI * 2 + _so, a_hi + _ga);                         \
                CP_ASYNC16(_bb + GALO * 2 + _so, a_lo + _ga);                         \
                CP_ASYNC16(_bb + GWHI * 2 + _so, w_hi + _gw);                         \
                CP_ASYNC16(_bb + GWLO * 2 + _so, w_lo + _gw);                         \
            }                                                                         \
        } while (0)

    LOAD_CHUNK(0, 0);
    CP_COMMIT();

    for (int t = 0; t < NCHUNK; ++t) {
        const int buf = t & 1;
        CP_WAIT0();          // load t landed (issued last iteration, overlapped)
        __syncthreads();     // publish buf t; compute t-1 done before overwriting buf^1
        if (t < NCHUNK - 1) {
            LOAD_CHUNK((t + 1) * 32, buf ^ 1);
            CP_COMMIT();
        }

        const uint32_t ahB = smb + (uint32_t)(buf * GM_BUF + GAHI) * 2;
        const uint32_t alB = smb + (uint32_t)(buf * GM_BUF + GALO) * 2;
        const uint32_t whB = smb + (uint32_t)(buf * GM_BUF + GWHI) * 2;
        const uint32_t wlB = smb + (uint32_t)(buf * GM_BUF + GWLO) * 2;

        #pragma unroll
        for (int ks = 0; ks < 2; ++ks) {
            uint32_t ah[4][4], al[4][4], wh2[2][4], wl2[2][4];
            #pragma unroll
            for (int mt = 0; mt < 4; ++mt) {
                const uint32_t off =
                    (uint32_t)((wm * 64 + mt * 16 + a_r) * LDT2 + ks * 16 + a_k) * 2;
                ldsm4(ah[mt][0], ah[mt][1], ah[mt][2], ah[mt][3], ahB + off);
                ldsm4(al[mt][0], al[mt][1], al[mt][2], al[mt][3], alB + off);
            }
            #pragma unroll
            for (int np2 = 0; np2 < 2; ++np2) {
                const uint32_t off =
                    (uint32_t)((wn * 32 + np2 * 16 + b_r) * LDT2 + ks * 16 + b_k) * 2;
                ldsm4(wh2[np2][0], wh2[np2][1], wh2[np2][2], wh2[np2][3], whB + off);
                ldsm4(wl2[np2][0], wl2[np2][1], wl2[np2][2], wl2[np2][3], wlB + off);
            }
            #pragma unroll
            for (int mt = 0; mt < 4; ++mt)
                #pragma unroll
                for (int nt = 0; nt < 4; ++nt)
                    mma16816(acc[mt][nt], ah[mt],
                             wh2[nt >> 1][(nt & 1) * 2], wh2[nt >> 1][(nt & 1) * 2 + 1]);
            #pragma unroll
            for (int mt = 0; mt < 4; ++mt)
                #pragma unroll
                for (int nt = 0; nt < 4; ++nt)
                    mma16816(acc[mt][nt], al[mt],
                             wh2[nt >> 1][(nt & 1) * 2], wh2[nt >> 1][(nt & 1) * 2 + 1]);
            #pragma unroll
            for (int mt = 0; mt < 4; ++mt)
                #pragma unroll
                for (int nt = 0; nt < 4; ++nt)
                    mma16816(acc[mt][nt], ah[mt],
                             wl2[nt >> 1][(nt & 1) * 2], wl2[nt >> 1][(nt & 1) * 2 + 1]);
        }
    }
    #undef LOAD_CHUNK

    #pragma unroll
    for (int mt = 0; mt < 4; ++mt) {
        const int r0 = rowBase + wm * 64 + mt * 16 + (lane >> 2);
        #pragma unroll
        for (int nt = 0; nt < 4; ++nt) {
            const int c = colBase + wn * 32 + nt * 8 + (lane & 3) * 2;
            const float2 bv = *(const float2*)&bias[c];
            float vx0 = acc[mt][nt][0] + bv.x, vy0 = acc[mt][nt][1] + bv.y;
            float vx1 = acc[mt][nt][2] + bv.x, vy1 = acc[mt][nt][3] + bv.y;
            if (MODE == 0) {
                const int tsel = c / CDIM;
                const int rem  = c - tsel * CDIM;
                const int hh = rem >> 6, d = rem & 63;
                const int m0 = r0, b0 = m0 >> 11, n0 = m0 & 2047;
                const int n1 = n0 + 8;
                if (tsel == 0) { vx0 *= QSCALE; vy0 *= QSCALE; vx1 *= QSCALE; vy1 *= QSCALE; }
                __nv_bfloat16 h00 = bhi(vx0), h01 = bhi(vy0), h10 = bhi(vx1), h11 = bhi(vy1);
                __nv_bfloat16* dh = (tsel == 0) ? g_qhi : (tsel == 1) ? g_khi : g_vhi;
                __nv_bfloat16* dl = (tsel == 0) ? g_qlo : (tsel == 1) ? g_klo : g_vlo;
                const size_t i0 = (((size_t)b0 * HEADS + hh) * SEQ + n0) * DH + d;
                const size_t i1 = (((size_t)b0 * HEADS + hh) * SEQ + n1) * DH + d;
                *(__nv_bfloat162*)&dh[i0] = __nv_bfloat162(h00, h01);
                *(__nv_bfloat162*)&dl[i0] = __nv_bfloat162(blo(vx0, h00), blo(vy0, h01));
                *(__nv_bfloat162*)&dh[i1] = __nv_bfloat162(h10, h11);
                *(__nv_bfloat162*)&dl[i1] = __nv_bfloat162(blo(vx1, h10), blo(vy1, h11));
            } else {
                float2 v0, v1;
                v0.x = vx0; v0.y = vy0; v1.x = vx1; v1.y = vy1;
                *(float2*)&out[(size_t)r0 * CDIM + c] = v0;
                *(float2*)&out[(size_t)(r0 + 8) * CDIM + c] = v1;
            }
        }
    }
}

// ---------------------------------------------------------------------------
// HMMA flash attention v5.1: round-10 v5 with single-sync pipeline
// (1 barrier per k-tile instead of 2). 64q x 64k, 3 CTAs/SM.
// ---------------------------------------------------------------------------
#define QLD 72
#define MSZ (64 * QLD)
#define BKHI 0
#define BKLO MSZ
#define BVHI (2 * MSZ)
#define BVLO (3 * MSZ)
#define BUFSZ (4 * MSZ)
#define ATTN_SMEM (2 * BUFSZ * 2)   // 73728 bytes

__global__ void __launch_bounds__(128, 3)
attn_kernel()
{
    extern __shared__ __nv_bfloat16 sm[];
    const uint32_t smb = smem_u32(sm);

    const int q0 = blockIdx.x * 64;
    const int h  = blockIdx.y;
    const int b  = blockIdx.z;
    const size_t base = ((size_t)(b * HEADS + h)) * SEQ * DH;

    const int tid  = threadIdx.x;
    const int lane = tid & 31;
    const int wrp  = tid >> 5;
    const int wq   = wrp * 16;

    const int a_r = lane & 15;
    const int a_k = (lane >> 4) * 8;
    const int b_r = (lane & 7) + ((lane >> 4) << 3);
    const int b_k = ((lane >> 3) & 1) * 8;
    const int v_k = (lane & 7) + (((lane >> 3) & 1) << 3);
    const int v_d = (lane >> 4) * 8;
    const int qr  = lane >> 2;
    const int qc  = (lane & 3) * 2;

    uint32_t qh[4][4], ql[4][4];
    {
        #pragma unroll
        for (int i = 0; i < 4; ++i) {
            const int idx = i * 128 + tid;
            const int r = idx >> 3, c8 = idx & 7;
            *(uint4*)&sm[r * QLD + c8 * 8] =
                *(const uint4*)&g_qhi[base + (size_t)(q0 + r) * DH + c8 * 8];
            *(uint4*)&sm[MSZ + r * QLD + c8 * 8] =
                *(const uint4*)&g_qlo[base + (size_t)(q0 + r) * DH + c8 * 8];
        }
        __syncthreads();
        #pragma unroll
        for (int ks = 0; ks < 4; ++ks) {
            ldsm4(qh[ks][0], qh[ks][1], qh[ks][2], qh[ks][3],
                  smb + (uint32_t)((wq + a_r) * QLD + ks * 16 + a_k) * 2);
            ldsm4(ql[ks][0], ql[ks][1], ql[ks][2], ql[ks][3],
                  smb + (uint32_t)(MSZ + (wq + a_r) * QLD + ks * 16 + a_k) * 2);
        }
        __syncthreads();   // Q reads done before cp.async overwrites buffer 0
    }

    #define LOAD_TILE(k0, buf)                                                        \
        do {                                                                          \
            const uint32_t _bb = smb + (uint32_t)((buf) * BUFSZ) * 2;                 \
            const __nv_bfloat16* _kh = g_khi + base + (size_t)(k0) * DH;              \
            const __nv_bfloat16* _kl = g_klo + base + (size_t)(k0) * DH;              \
            const __nv_bfloat16* _vh = g_vhi + base + (size_t)(k0) * DH;              \
            const __nv_bfloat16* _vl = g_vlo + base + (size_t)(k0) * DH;              \
            _Pragma("unroll")                                                         \
            for (int _i = 0; _i < 4; ++_i) {                                          \
                const int _idx = _i * 128 + tid;                                      \
                const int _r = _idx >> 3, _c = _idx & 7;                              \
                const uint32_t _so = (uint32_t)(_r * QLD + _c * 8) * 2;               \
                const size_t _go = (size_t)_r * 64 + _c * 8;                          \
                CP_ASYNC16(_bb + BKHI * 2 + _so, _kh + _go);                          \
                CP_ASYNC16(_bb + BKLO * 2 + _so, _kl + _go);                          \
                CP_ASYNC16(_bb + BVHI * 2 + _so, _vh + _go);                          \
                CP_ASYNC16(_bb + BVLO * 2 + _so, _vl + _go);                          \
            }                                                                         \
        } while (0)

    LOAD_TILE(0, 0);
    CP_COMMIT();

    float m_i[2] = {-1e30f, -1e30f};
    float l_i[2] = {0.f, 0.f};
    float oacc[8][4] = {};

    for (int t = 0; t < 32; ++t) {
        const int buf = t & 1;
        CP_WAIT0();          // tile t landed
        __syncthreads();     // publish tile t; compute t-1 done before overwrite
        if (t < 31) {
            LOAD_TILE((t + 1) * 64, buf ^ 1);
            CP_COMMIT();
        }

        const uint32_t kh = smb + (uint32_t)(buf * BUFSZ + BKHI) * 2;
        const uint32_t kl = smb + (uint32_t)(buf * BUFSZ + BKLO) * 2;
        const uint32_t vh = smb + (uint32_t)(buf * BUFSZ + BVHI) * 2;
        const uint32_t vl = smb + (uint32_t)(buf * BUFSZ + BVLO) * 2;

        // ---- S = QK^T ----
        float sacc[8][4] = {};
        #pragma unroll
        for (int ks = 0; ks < 4; ++ks) {
            #pragma unroll
            for (int ng = 0; ng < 4; ++ng) {
                uint32_t bf[4];
                ldsm4(bf[0], bf[1], bf[2], bf[3],
                      kh + (uint32_t)((ng * 16 + b_r) * QLD + ks * 16 + b_k) * 2);
                mma16816(sacc[ng * 2 + 0], qh[ks], bf[0], bf[1]);
                mma16816(sacc[ng * 2 + 1], qh[ks], bf[2], bf[3]);
                mma16816(sacc[ng * 2 + 0], ql[ks], bf[0], bf[1]);
                mma16816(sacc[ng * 2 + 1], ql[ks], bf[2], bf[3]);
            }
        }
        #pragma unroll
        for (int ks = 0; ks < 4; ++ks) {
            #pragma unroll
            for (int ng = 0; ng < 4; ++ng) {
                uint32_t bf[4];
                ldsm4(bf[0], bf[1], bf[2], bf[3],
                      kl + (uint32_t)((ng * 16 + b_r) * QLD + ks * 16 + b_k) * 2);
                mma16816(sacc[ng * 2 + 0], qh[ks], bf[0], bf[1]);
                mma16816(sacc[ng * 2 + 1], qh[ks], bf[2], bf[3]);
            }
        }

        // ---- online softmax (exp2 domain, warp-local rows qr, qr+8) ----
        #pragma unroll
        for (int ri = 0; ri < 2; ++ri) {
            float mx = -1e30f;
            #pragma unroll
            for (int nt = 0; nt < 8; ++nt) {
                mx = fmaxf(mx, sacc[nt][ri * 2 + 0]);
                mx = fmaxf(mx, sacc[nt][ri * 2 + 1]);
            }
            mx = fmaxf(mx, __shfl_xor_sync(0xffffffffu, mx, 1));
            mx = fmaxf(mx, __shfl_xor_sync(0xffffffffu, mx, 2));
            const float mn = fmaxf(m_i[ri], mx);
            const float alpha = ex2f(m_i[ri] - mn);
            m_i[ri] = mn;
            float r = 0.f;
            #pragma unroll
            for (int nt = 0; nt < 8; ++nt) {
                float p0 = ex2f(sacc[nt][ri * 2 + 0] - mn);
                float p1 = ex2f(sacc[nt][ri * 2 + 1] - mn);
                sacc[nt][ri * 2 + 0] = p0;
                sacc[nt][ri * 2 + 1] = p1;
                r += p0 + p1;
            }
            r += __shfl_xor_sync(0xffffffffu, r, 1);
            r += __shfl_xor_sync(0xffffffffu, r, 2);
            l_i[ri] = l_i[ri] * alpha + r;
            #pragma unroll
            for (int nt = 0; nt < 8; ++nt) {
                oacc[nt][ri * 2 + 0] *= alpha;
                oacc[nt][ri * 2 + 1] *= alpha;
            }
        }

        // ---- PV: P frags from sacc, V frags via ldmatrix.trans ----
        #pragma unroll
        for (int ks = 0; ks < 4; ++ks) {
            uint32_t ph[4], pl[4];
            {
                const float s00 = sacc[2 * ks][0],     s01 = sacc[2 * ks][1];
                const float s02 = sacc[2 * ks][2],     s03 = sacc[2 * ks][3];
                const float s10 = sacc[2 * ks + 1][0], s11 = sacc[2 * ks + 1][1];
                const float s12 = sacc[2 * ks + 1][2], s13 = sacc[2 * ks + 1][3];
                ph[0] = packbf(s00, s01);
                ph[1] = packbf(s02, s03);
                ph[2] = packbf(s10, s11);
                ph[3] = packbf(s12, s13);
                pl[0] = packbf(s00 - __uint_as_float(ph[0] << 16),
                               s01 - __uint_as_float(ph[0] & 0xffff0000u));
                pl[1] = packbf(s02 - __uint_as_float(ph[1] << 16),
                               s03 - __uint_as_float(ph[1] & 0xffff0000u));
                pl[2] = packbf(s10 - __uint_as_float(ph[2] << 16),
                               s11 - __uint_as_float(ph[2] & 0xffff0000u));
                pl[3] = packbf(s12 - __uint_as_float(ph[3] << 16),
                               s13 - __uint_as_float(ph[3] & 0xffff0000u));
            }
            const uint32_t vrow = (uint32_t)((ks * 16 + v_k) * QLD) * 2;
            #pragma unroll
            for (int ng = 0; ng < 4; ++ng) {
                uint32_t bh[4], bl[4];
                const uint32_t voff = vrow + (uint32_t)(ng * 16 + v_d) * 2;
                ldsm4t(bh[0], bh[1], bh[2], bh[3], vh + voff);
                ldsm4t(bl[0], bl[1], bl[2], bl[3], vl + voff);
                mma16816(oacc[ng * 2 + 0], ph, bh[0], bh[1]);
                mma16816(oacc[ng * 2 + 1], ph, bh[2], bh[3]);
                mma16816(oacc[ng * 2 + 0], ph, bl[0], bl[1]);
                mma16816(oacc[ng * 2 + 1], ph, bl[2], bl[3]);
                mma16816(oacc[ng * 2 + 0], pl, bh[0], bh[1]);
                mma16816(oacc[ng * 2 + 1], pl, bh[2], bh[3]);
            }
        }
    }

    // ---- epilogue: normalize, split hi/lo, write a_hi/a_lo [B,N,C] ----
    const float inv0 = 1.f / l_i[0];
    const float inv1 = 1.f / l_i[1];
    const int row0 = q0 + wq + qr;
    #pragma unroll
    for (int nt = 0; nt < 8; ++nt) {
        const int col = h * DH + nt * 8 + qc;
        const size_t i0 = ((size_t)b * SEQ + row0) * CDIM + col;
        const size_t i1 = ((size_t)b * SEQ + row0 + 8) * CDIM + col;
        float o00 = oacc[nt][0] * inv0, o01 = oacc[nt][1] * inv0;
        float o10 = oacc[nt][2] * inv1, o11 = oacc[nt][3] * inv1;
        __nv_bfloat16 h00 = bhi(o00), h01 = bhi(o01), h10 = bhi(o10), h11 = bhi(o11);
        *(__nv_bfloat162*)&g_a_hi[i0] = __nv_bfloat162(h00, h01);
        *(__nv_bfloat162*)&g_a_lo[i0] = __nv_bfloat162(blo(o00, h00), blo(o01, h01));
        *(__nv_bfloat162*)&g_a_hi[i1] = __nv_bfloat162(h10, h11);
        *(__nv_bfloat162*)&g_a_lo[i1] = __nv_bfloat162(blo(o10, h10), blo(o11, h11));
    }
    #undef LOAD_TILE
}

// ---------------------------------------------------------------------------
extern "C" void kernel_launch(void* const* d_in, const int* in_sizes, int n_in,
                              void* d_out, int out_size)
{
    const float* x      = (const float*)d_in[0];
    const float* qkv_w  = (const float*)d_in[1];
    const float* qkv_b  = (const float*)d_in[2];
    const float* proj_w = (const float*)d_in[3];
    const float* proj_b = (const float*)d_in[4];
    float* out = (float*)d_out;

    cudaFuncSetAttribute(mma_gemm<0>, cudaFuncAttributeMaxDynamicSharedMemorySize, GEMM_SMEM);
    cudaFuncSetAttribute(mma_gemm<1>, cudaFuncAttributeMaxDynamicSharedMemorySize, GEMM_SMEM);
    cudaFuncSetAttribute(attn_kernel, cudaFuncAttributeMaxDynamicSharedMemorySize, ATTN_SMEM);

    __nv_bfloat16 *a_hi, *a_lo, *w_hi, *w_lo, *w2_hi, *w2_lo;
    cudaGetSymbolAddress((void**)&a_hi, g_a_hi);
    cudaGetSymbolAddress((void**)&a_lo, g_a_lo);
    cudaGetSymbolAddress((void**)&w_hi, g_w_hi);
    cudaGetSymbolAddress((void**)&w_lo, g_w_lo);
    cudaGetSymbolAddress((void**)&w2_hi, g_w2_hi);
    cudaGetSymbolAddress((void**)&w2_lo, g_w2_lo);

    const int nx4 = MTOT * CDIM / 4;
    const int nw4 = 3 * CDIM * CDIM / 4;
    const int np4 = CDIM * CDIM / 4;

    split_kernel<<<(nx4 + 255) / 256, 256>>>((const float4*)x,
        (__nv_bfloat162*)a_hi, (__nv_bfloat162*)a_lo, nx4);
    split_kernel<<<(nw4 + 255) / 256, 256>>>((const float4*)qkv_w,
        (__nv_bfloat162*)w_hi, (__nv_bfloat162*)w_lo, nw4);
    split_kernel<<<(np4 + 255) / 256, 256>>>((const float4*)proj_w,
        (__nv_bfloat162*)w2_hi, (__nv_bfloat162*)w2_lo, np4);

    mma_gemm<0><<<dim3(18, 64), 256, GEMM_SMEM>>>(a_hi, a_lo, w_hi, w_lo, qkv_b, nullptr);

    attn_kernel<<<dim3(SEQ / 64, HEADS, BATCH), 128, ATTN_SMEM>>>();

    mma_gemm<1><<<dim3(6, 64), 256, GEMM_SMEM>>>(a_hi, a_lo, w2_hi, w2_lo, proj_b, out);
}

// round 15
// speedup vs baseline: 1.1727x; 1.1596x over previous
#include <cuda_runtime.h>
#include <cuda_bf16.h>
#include <cuda_fp16.h>
#include <cstdint>

#define HEADS 12
#define SEQ   2048
#define BATCH 4
#define DH    64
#define CDIM  768
#define MTOT  8192   // BATCH*SEQ
#define NQKV ((size_t)BATCH * HEADS * SEQ * DH)

// ---------------- scratch (allocation-free) ----------------
// attention operands stay bf16 hi/lo (3-product path, proven accurate)
__device__ __align__(16) __nv_bfloat16 g_qhi[NQKV], g_qlo[NQKV];
__device__ __align__(16) __nv_bfloat16 g_khi[NQKV], g_klo[NQKV];
__device__ __align__(16) __nv_bfloat16 g_vhi[NQKV], g_vlo[NQKV];
// GEMM activations: single fp16 (x, then attn output); weights fp16 hi/lo (x1024)
__device__ __align__(16) __half g_a[(size_t)MTOT * CDIM];
__device__ __align__(16) __half g_w_hi[(size_t)3 * CDIM * CDIM];
__device__ __align__(16) __half g_w_lo[(size_t)3 * CDIM * CDIM];
__device__ __align__(16) __half g_w2_hi[(size_t)CDIM * CDIM];
__device__ __align__(16) __half g_w2_lo[(size_t)CDIM * CDIM];

// Q prescale: 1/sqrt(64) * log2(e)  (softmax runs in exp2 domain)
#define QSCALE 0.1803368801111204f
#define WSCALE 1024.0f
#define INVW   (1.0f / 1024.0f)

// ---------------- helpers ----------------
__device__ __forceinline__ uint32_t smem_u32(const void* p) {
    uint32_t a;
    asm("{ .reg .u64 t; cvta.to.shared.u64 t, %1; cvt.u32.u64 %0, t; }" : "=r"(a) : "l"(p));
    return a;
}
__device__ __forceinline__ void ldsm4(uint32_t& r0, uint32_t& r1, uint32_t& r2, uint32_t& r3,
                                      uint32_t addr) {
    asm volatile("ldmatrix.sync.aligned.m8n8.x4.shared.b16 {%0,%1,%2,%3}, [%4];"
                 : "=r"(r0), "=r"(r1), "=r"(r2), "=r"(r3) : "r"(addr));
}
__device__ __forceinline__ void ldsm4t(uint32_t& r0, uint32_t& r1, uint32_t& r2, uint32_t& r3,
                                       uint32_t addr) {
    asm volatile("ldmatrix.sync.aligned.m8n8.x4.trans.shared.b16 {%0,%1,%2,%3}, [%4];"
                 : "=r"(r0), "=r"(r1), "=r"(r2), "=r"(r3) : "r"(addr));
}
// bf16 mma (attention)
__device__ __forceinline__ void mma16816(float* c, const uint32_t* a, uint32_t b0, uint32_t b1) {
    asm volatile("mma.sync.aligned.m16n8k16.row.col.f32.bf16.bf16.f32 "
                 "{%0,%1,%2,%3}, {%4,%5,%6,%7}, {%8,%9}, {%0,%1,%2,%3};"
                 : "+f"(c[0]), "+f"(c[1]), "+f"(c[2]), "+f"(c[3])
                 : "r"(a[0]), "r"(a[1]), "r"(a[2]), "r"(a[3]), "r"(b0), "r"(b1));
}
// fp16 mma (GEMMs)
__device__ __forceinline__ void mma16816h(float* c, const uint32_t* a, uint32_t b0, uint32_t b1) {
    asm volatile("mma.sync.aligned.m16n8k16.row.col.f32.f16.f16.f32 "
                 "{%0,%1,%2,%3}, {%4,%5,%6,%7}, {%8,%9}, {%0,%1,%2,%3};"
                 : "+f"(c[0]), "+f"(c[1]), "+f"(c[2]), "+f"(c[3])
                 : "r"(a[0]), "r"(a[1]), "r"(a[2]), "r"(a[3]), "r"(b0), "r"(b1));
}
__device__ __forceinline__ __nv_bfloat16 bhi(float x) { return __float2bfloat16(x); }
__device__ __forceinline__ __nv_bfloat16 blo(float x, __nv_bfloat16 h) {
    return __float2bfloat16(x - __bfloat162float(h));
}
__device__ __forceinline__ float ex2f(float x) {
    float y;
    asm("ex2.approx.f32 %0, %1;" : "=f"(y) : "f"(x));
    return y;
}
__device__ __forceinline__ uint32_t packbf(float lo_, float hi_) {
    uint32_t r;
    asm("cvt.rn.bf16x2.f32 %0, %1, %2;" : "=r"(r) : "f"(hi_), "f"(lo_));
    return r;
}

#define CP_ASYNC16(dst, src) \
    asm volatile("cp.async.cg.shared.global [%0], [%1], 16;" :: "r"(dst), "l"(src))
#define CP_COMMIT() asm volatile("cp.async.commit_group;")
#define CP_WAIT0()  asm volatile("cp.async.wait_group 0;")

// ---------------------------------------------------------------------------
// x -> fp16 (round only; dropped xl term is the 2.4e-4 error budget)
__global__ void cvt_half(const float4* __restrict__ src, __half2* __restrict__ dst, int n4)
{
    int i = blockIdx.x * 256 + threadIdx.x;
    if (i < n4) {
        float4 v = src[i];
        dst[2 * i]     = __floats2half2_rn(v.x, v.y);
        dst[2 * i + 1] = __floats2half2_rn(v.z, v.w);
    }
}
// w*1024 -> fp16 hi + lo
__global__ void split_half(const float4* __restrict__ src,
                           __half2* __restrict__ hi, __half2* __restrict__ lo, int n4)
{
    int i = blockIdx.x * 256 + threadIdx.x;
    if (i < n4) {
        float4 v = src[i];
        float sx = v.x * WSCALE, sy = v.y * WSCALE, sz = v.z * WSCALE, sw = v.w * WSCALE;
        __half hx = __float2half_rn(sx), hy = __float2half_rn(sy);
        __half hz = __float2half_rn(sz), hw = __float2half_rn(sw);
        hi[2 * i]     = __halves2half2(hx, hy);
        hi[2 * i + 1] = __halves2half2(hz, hw);
        lo[2 * i]     = __floats2half2_rn(sx - __half2float(hx), sy - __half2float(hy));
        lo[2 * i + 1] = __floats2half2_rn(sz - __half2float(hz), sw - __half2float(hw));
    }
}

// ---------------------------------------------------------------------------
// fp16x2 GEMM: C = (A @ (Whi+Wlo)^T) / 1024 + bias. 2 MMA products.
// Smem: A[128][40] + WH[128][40] + WL[128][40] per buffer, double-buffered.
// MODE 0: split epilogue -> Q(prescaled)/K/V bf16 hi/lo; MODE 1: fp32 out.
// ---------------------------------------------------------------------------
#define LDT2 40
#define GM_MSZ (128 * LDT2)
#define GA   0
#define GWHI GM_MSZ
#define GWLO (2 * GM_MSZ)
#define GM_BUF (3 * GM_MSZ)
#define GEMM_SMEM (2 * GM_BUF * 2)     // 61440 bytes
#define NCHUNK 24

template <int MODE>
__global__ void __launch_bounds__(256, 2)
mma_gemm(const __half* __restrict__ a, const __half* __restrict__ w_hi,
         const __half* __restrict__ w_lo, const float* __restrict__ bias,
         float* __restrict__ out)
{
    extern __shared__ __half sm[];
    const uint32_t smb = smem_u32(sm);
    const int tid  = threadIdx.x;
    const int lane = tid & 31;
    const int wrp  = tid >> 5;
    const int wm   = wrp & 1;
    const int wn   = wrp >> 1;
    const int rowBase = blockIdx.y * 128;
    const int colBase = blockIdx.x * 128;

    const int a_r = lane & 15;
    const int a_k = (lane >> 4) * 8;
    const int b_r = (lane & 7) + ((lane >> 4) << 3);
    const int b_k = ((lane >> 3) & 1) * 8;

    float acc[4][4][4] = {};

    #define LOAD_CHUNK(kk, buf)                                                       \
        do {                                                                          \
            const uint32_t _bb = smb + (uint32_t)((buf) * GM_BUF) * 2;                \
            _Pragma("unroll")                                                         \
            for (int _i = 0; _i < 2; ++_i) {                                          \
                const int _idx = _i * 256 + tid;                                      \
                const int _r = _idx >> 2, _c = _idx & 3;                              \
                const size_t _ga = (size_t)(rowBase + _r) * CDIM + (kk) + _c * 8;     \
                const size_t _gw = (size_t)(colBase + _r) * CDIM + (kk) + _c * 8;     \
                const uint32_t _so = (uint32_t)(_r * LDT2 + _c * 8) * 2;              \
                CP_ASYNC16(_bb + GA * 2 + _so, a + _ga);                              \
                CP_ASYNC16(_bb + GWHI * 2 + _so, w_hi + _gw);                         \
                CP_ASYNC16(_bb + GWLO * 2 + _so, w_lo + _gw);                         \
            }                                                                         \
        } while (0)

    LOAD_CHUNK(0, 0);
    CP_COMMIT();

    for (int t = 0; t < NCHUNK; ++t) {
        const int buf = t & 1;
        CP_WAIT0();
        __syncthreads();
        if (t < NCHUNK - 1) {
            LOAD_CHUNK((t + 1) * 32, buf ^ 1);
            CP_COMMIT();
        }

        const uint32_t aB  = smb + (uint32_t)(buf * GM_BUF + GA) * 2;
        const uint32_t whB = smb + (uint32_t)(buf * GM_BUF + GWHI) * 2;
        const uint32_t wlB = smb + (uint32_t)(buf * GM_BUF + GWLO) * 2;

        #pragma unroll
        for (int ks = 0; ks < 2; ++ks) {
            uint32_t ah[4][4], wh2[2][4], wl2[2][4];
            #pragma unroll
            for (int mt = 0; mt < 4; ++mt) {
                const uint32_t off =
                    (uint32_t)((wm * 64 + mt * 16 + a_r) * LDT2 + ks * 16 + a_k) * 2;
                ldsm4(ah[mt][0], ah[mt][1], ah[mt][2], ah[mt][3], aB + off);
            }
            #pragma unroll
            for (int np2 = 0; np2 < 2; ++np2) {
                const uint32_t off =
                    (uint32_t)((wn * 32 + np2 * 16 + b_r) * LDT2 + ks * 16 + b_k) * 2;
                ldsm4(wh2[np2][0], wh2[np2][1], wh2[np2][2], wh2[np2][3], whB + off);
                ldsm4(wl2[np2][0], wl2[np2][1], wl2[np2][2], wl2[np2][3], wlB + off);
            }
            #pragma unroll
            for (int mt = 0; mt < 4; ++mt)
                #pragma unroll
                for (int nt = 0; nt < 4; ++nt)
                    mma16816h(acc[mt][nt], ah[mt],
                              wh2[nt >> 1][(nt & 1) * 2], wh2[nt >> 1][(nt & 1) * 2 + 1]);
            #pragma unroll
            for (int mt = 0; mt < 4; ++mt)
                #pragma unroll
                for (int nt = 0; nt < 4; ++nt)
                    mma16816h(acc[mt][nt], ah[mt],
                              wl2[nt >> 1][(nt & 1) * 2], wl2[nt >> 1][(nt & 1) * 2 + 1]);
        }
    }
    #undef LOAD_CHUNK

    #pragma unroll
    for (int mt = 0; mt < 4; ++mt) {
        const int r0 = rowBase + wm * 64 + mt * 16 + (lane >> 2);
        #pragma unroll
        for (int nt = 0; nt < 4; ++nt) {
            const int c = colBase + wn * 32 + nt * 8 + (lane & 3) * 2;
            const float2 bv = *(const float2*)&bias[c];
            float vx0 = acc[mt][nt][0] * INVW + bv.x, vy0 = acc[mt][nt][1] * INVW + bv.y;
            float vx1 = acc[mt][nt][2] * INVW + bv.x, vy1 = acc[mt][nt][3] * INVW + bv.y;
            if (MODE == 0) {
                const int tsel = c / CDIM;
                const int rem  = c - tsel * CDIM;
                const int hh = rem >> 6, d = rem & 63;
                const int m0 = r0, b0 = m0 >> 11, n0 = m0 & 2047;
                const int n1 = n0 + 8;
                if (tsel == 0) { vx0 *= QSCALE; vy0 *= QSCALE; vx1 *= QSCALE; vy1 *= QSCALE; }
                __nv_bfloat16 h00 = bhi(vx0), h01 = bhi(vy0), h10 = bhi(vx1), h11 = bhi(vy1);
                __nv_bfloat16* dh = (tsel == 0) ? g_qhi : (tsel == 1) ? g_khi : g_vhi;
                __nv_bfloat16* dl = (tsel == 0) ? g_qlo : (tsel == 1) ? g_klo : g_vlo;
                const size_t i0 = (((size_t)b0 * HEADS + hh) * SEQ + n0) * DH + d;
                const size_t i1 = (((size_t)b0 * HEADS + hh) * SEQ + n1) * DH + d;
                *(__nv_bfloat162*)&dh[i0] = __nv_bfloat162(h00, h01);
                *(__nv_bfloat162*)&dl[i0] = __nv_bfloat162(blo(vx0, h00), blo(vy0, h01));
                *(__nv_bfloat162*)&dh[i1] = __nv_bfloat162(h10, h11);
                *(__nv_bfloat162*)&dl[i1] = __nv_bfloat162(blo(vx1, h10), blo(vy1, h11));
            } else {
                float2 v0, v1;
                v0.x = vx0; v0.y = vy0; v1.x = vx1; v1.y = vy1;
                *(float2*)&out[(size_t)r0 * CDIM + c] = v0;
                *(float2*)&out[(size_t)(r0 + 8) * CDIM + c] = v1;
            }
        }
    }
}

// ---------------------------------------------------------------------------
// HMMA flash attention (bf16 x3, unchanged math): 64q x 64k, 3 CTAs/SM.
// Epilogue now writes a single fp16 activation tensor for the proj GEMM.
// ---------------------------------------------------------------------------
#define QLD 72
#define MSZ (64 * QLD)
#define BKHI 0
#define BKLO MSZ
#define BVHI (2 * MSZ)
#define BVLO (3 * MSZ)
#define BUFSZ (4 * MSZ)
#define ATTN_SMEM (2 * BUFSZ * 2)   // 73728 bytes

__global__ void __launch_bounds__(128, 3)
attn_kernel()
{
    extern __shared__ __nv_bfloat16 smA[];
    const uint32_t smb = smem_u32(smA);

    const int q0 = blockIdx.x * 64;
    const int h  = blockIdx.y;
    const int b  = blockIdx.z;
    const size_t base = ((size_t)(b * HEADS + h)) * SEQ * DH;

    const int tid  = threadIdx.x;
    const int lane = tid & 31;
    const int wrp  = tid >> 5;
    const int wq   = wrp * 16;

    const int a_r = lane & 15;
    const int a_k = (lane >> 4) * 8;
    const int b_r = (lane & 7) + ((lane >> 4) << 3);
    const int b_k = ((lane >> 3) & 1) * 8;
    const int v_k = (lane & 7) + (((lane >> 3) & 1) << 3);
    const int v_d = (lane >> 4) * 8;
    const int qr  = lane >> 2;
    const int qc  = (lane & 3) * 2;

    uint32_t qh[4][4], ql[4][4];
    {
        #pragma unroll
        for (int i = 0; i < 4; ++i) {
            const int idx = i * 128 + tid;
            const int r = idx >> 3, c8 = idx & 7;
            *(uint4*)&smA[r * QLD + c8 * 8] =
                *(const uint4*)&g_qhi[base + (size_t)(q0 + r) * DH + c8 * 8];
            *(uint4*)&smA[MSZ + r * QLD + c8 * 8] =
                *(const uint4*)&g_qlo[base + (size_t)(q0 + r) * DH + c8 * 8];
        }
        __syncthreads();
        #pragma unroll
        for (int ks = 0; ks < 4; ++ks) {
            ldsm4(qh[ks][0], qh[ks][1], qh[ks][2], qh[ks][3],
                  smb + (uint32_t)((wq + a_r) * QLD + ks * 16 + a_k) * 2);
            ldsm4(ql[ks][0], ql[ks][1], ql[ks][2], ql[ks][3],
                  smb + (uint32_t)(MSZ + (wq + a_r) * QLD + ks * 16 + a_k) * 2);
        }
        __syncthreads();
    }

    #define LOAD_TILE(k0, buf)                                                        \
        do {                                                                          \
            const uint32_t _bb = smb + (uint32_t)((buf) * BUFSZ) * 2;                 \
            const __nv_bfloat16* _kh = g_khi + base + (size_t)(k0) * DH;              \
            const __nv_bfloat16* _kl = g_klo + base + (size_t)(k0) * DH;              \
            const __nv_bfloat16* _vh = g_vhi + base + (size_t)(k0) * DH;              \
            const __nv_bfloat16* _vl = g_vlo + base + (size_t)(k0) * DH;              \
            _Pragma("unroll")                                                         \
            for (int _i = 0; _i < 4; ++_i) {                                          \
                const int _idx = _i * 128 + tid;                                      \
                const int _r = _idx >> 3, _c = _idx & 7;                              \
                const uint32_t _so = (uint32_t)(_r * QLD + _c * 8) * 2;               \
                const size_t _go = (size_t)_r * 64 + _c * 8;                          \
                CP_ASYNC16(_bb + BKHI * 2 + _so, _kh + _go);                          \
                CP_ASYNC16(_bb + BKLO * 2 + _so, _kl + _go);                          \
                CP_ASYNC16(_bb + BVHI * 2 + _so, _vh + _go);                          \
                CP_ASYNC16(_bb + BVLO * 2 + _so, _vl + _go);                          \
            }                                                                         \
        } while (0)

    LOAD_TILE(0, 0);
    CP_COMMIT();

    float m_i[2] = {-1e30f, -1e30f};
    float l_i[2] = {0.f, 0.f};
    float oacc[8][4] = {};

    for (int t = 0; t < 32; ++t) {
        const int buf = t & 1;
        CP_WAIT0();
        __syncthreads();
        if (t < 31) {
            LOAD_TILE((t + 1) * 64, buf ^ 1);
            CP_COMMIT();
        }

        const uint32_t kh = smb + (uint32_t)(buf * BUFSZ + BKHI) * 2;
        const uint32_t kl = smb + (uint32_t)(buf * BUFSZ + BKLO) * 2;
        const uint32_t vh = smb + (uint32_t)(buf * BUFSZ + BVHI) * 2;
        const uint32_t vl = smb + (uint32_t)(buf * BUFSZ + BVLO) * 2;

        float sacc[8][4] = {};
        #pragma unroll
        for (int ks = 0; ks < 4; ++ks) {
            #pragma unroll
            for (int ng = 0; ng < 4; ++ng) {
                uint32_t bf[4];
                ldsm4(bf[0], bf[1], bf[2], bf[3],
                      kh + (uint32_t)((ng * 16 + b_r) * QLD + ks * 16 + b_k) * 2);
                mma16816(sacc[ng * 2 + 0], qh[ks], bf[0], bf[1]);
                mma16816(sacc[ng * 2 + 1], qh[ks], bf[2], bf[3]);
                mma16816(sacc[ng * 2 + 0], ql[ks], bf[0], bf[1]);
                mma16816(sacc[ng * 2 + 1], ql[ks], bf[2], bf[3]);
            }
        }
        #pragma unroll
        for (int ks = 0; ks < 4; ++ks) {
            #pragma unroll
            for (int ng = 0; ng < 4; ++ng) {
                uint32_t bf[4];
                ldsm4(bf[0], bf[1], bf[2], bf[3],
                      kl + (uint32_t)((ng * 16 + b_r) * QLD + ks * 16 + b_k) * 2);
                mma16816(sacc[ng * 2 + 0], qh[ks], bf[0], bf[1]);
                mma16816(sacc[ng * 2 + 1], qh[ks], bf[2], bf[3]);
            }
        }

        #pragma unroll
        for (int ri = 0; ri < 2; ++ri) {
            float mx = -1e30f;
            #pragma unroll
            for (int nt = 0; nt < 8; ++nt) {
                mx = fmaxf(mx, sacc[nt][ri * 2 + 0]);
                mx = fmaxf(mx, sacc[nt][ri * 2 + 1]);
            }
            mx = fmaxf(mx, __shfl_xor_sync(0xffffffffu, mx, 1));
            mx = fmaxf(mx, __shfl_xor_sync(0xffffffffu, mx, 2));
            const float mn = fmaxf(m_i[ri], mx);
            const float alpha = ex2f(m_i[ri] - mn);
            m_i[ri] = mn;
            float r = 0.f;
            #pragma unroll
            for (int nt = 0; nt < 8; ++nt) {
                float p0 = ex2f(sacc[nt][ri * 2 + 0] - mn);
                float p1 = ex2f(sacc[nt][ri * 2 + 1] - mn);
                sacc[nt][ri * 2 + 0] = p0;
                sacc[nt][ri * 2 + 1] = p1;
                r += p0 + p1;
            }
            r += __shfl_xor_sync(0xffffffffu, r, 1);
            r += __shfl_xor_sync(0xffffffffu, r, 2);
            l_i[ri] = l_i[ri] * alpha + r;
            #pragma unroll
            for (int nt = 0; nt < 8; ++nt) {
                oacc[nt][ri * 2 + 0] *= alpha;
                oacc[nt][ri * 2 + 1] *= alpha;
            }
        }

        #pragma unroll
        for (int ks = 0; ks < 4; ++ks) {
            uint32_t ph[4], pl[4];
            {
                const float s00 = sacc[2 * ks][0],     s01 = sacc[2 * ks][1];
                const float s02 = sacc[2 * ks][2],     s03 = sacc[2 * ks][3];
                const float s10 = sacc[2 * ks + 1][0], s11 = sacc[2 * ks + 1][1];
                const float s12 = sacc[2 * ks + 1][2], s13 = sacc[2 * ks + 1][3];
                ph[0] = packbf(s00, s01);
                ph[1] = packbf(s02, s03);
                ph[2] = packbf(s10, s11);
                ph[3] = packbf(s12, s13);
                pl[0] = packbf(s00 - __uint_as_float(ph[0] << 16),
                               s01 - __uint_as_float(ph[0] & 0xffff0000u));
                pl[1] = packbf(s02 - __uint_as_float(ph[1] << 16),
                               s03 - __uint_as_float(ph[1] & 0xffff0000u));
                pl[2] = packbf(s10 - __uint_as_float(ph[2] << 16),
                               s11 - __uint_as_float(ph[2] & 0xffff0000u));
                pl[3] = packbf(s12 - __uint_as_float(ph[3] << 16),
                               s13 - __uint_as_float(ph[3] & 0xffff0000u));
            }
            const uint32_t vrow = (uint32_t)((ks * 16 + v_k) * QLD) * 2;
            #pragma unroll
            for (int ng = 0; ng < 4; ++ng) {
                uint32_t bh[4], bl[4];
                const uint32_t voff = vrow + (uint32_t)(ng * 16 + v_d) * 2;
                ldsm4t(bh[0], bh[1], bh[2], bh[3], vh + voff);
                ldsm4t(bl[0], bl[1], bl[2], bl[3], vl + voff);
                mma16816(oacc[ng * 2 + 0], ph, bh[0], bh[1]);
                mma16816(oacc[ng * 2 + 1], ph, bh[2], bh[3]);
                mma16816(oacc[ng * 2 + 0], ph, bl[0], bl[1]);
                mma16816(oacc[ng * 2 + 1], ph, bl[2], bl[3]);
                mma16816(oacc[ng * 2 + 0], pl, bh[0], bh[1]);
                mma16816(oacc[ng * 2 + 1], pl, bh[2], bh[3]);
            }
        }
    }

    // ---- epilogue: normalize, write single fp16 activation [B,N,C] ----
    const float inv0 = 1.f / l_i[0];
    const float inv1 = 1.f / l_i[1];
    const int row0 = q0 + wq + qr;
    #pragma unroll
    for (int nt = 0; nt < 8; ++nt) {
        const int col = h * DH + nt * 8 + qc;
        const size_t i0 = ((size_t)b * SEQ + row0) * CDIM + col;
        const size_t i1 = ((size_t)b * SEQ + row0 + 8) * CDIM + col;
        *(__half2*)&g_a[i0] = __floats2half2_rn(oacc[nt][0] * inv0, oacc[nt][1] * inv0);
        *(__half2*)&g_a[i1] = __floats2half2_rn(oacc[nt][2] * inv1, oacc[nt][3] * inv1);
    }
    #undef LOAD_TILE
}

// ---------------------------------------------------------------------------
extern "C" void kernel_launch(void* const* d_in, const int* in_sizes, int n_in,
                              void* d_out, int out_size)
{
    const float* x      = (const float*)d_in[0];
    const float* qkv_w  = (const float*)d_in[1];
    const float* qkv_b  = (const float*)d_in[2];
    const float* proj_w = (const float*)d_in[3];
    const float* proj_b = (const float*)d_in[4];
    float* out = (float*)d_out;

    cudaFuncSetAttribute(mma_gemm<0>, cudaFuncAttributeMaxDynamicSharedMemorySize, GEMM_SMEM);
    cudaFuncSetAttribute(mma_gemm<1>, cudaFuncAttributeMaxDynamicSharedMemorySize, GEMM_SMEM);
    cudaFuncSetAttribute(attn_kernel, cudaFuncAttributeMaxDynamicSharedMemorySize, ATTN_SMEM);

    __half *a_p, *w_hi, *w_lo, *w2_hi, *w2_lo;
    cudaGetSymbolAddress((void**)&a_p, g_a);
    cudaGetSymbolAddress((void**)&w_hi, g_w_hi);
    cudaGetSymbolAddress((void**)&w_lo, g_w_lo);
    cudaGetSymbolAddress((void**)&w2_hi, g_w2_hi);
    cudaGetSymbolAddress((void**)&w2_lo, g_w2_lo);

    const int nx4 = MTOT * CDIM / 4;
    const int nw4 = 3 * CDIM * CDIM / 4;
    const int np4 = CDIM * CDIM / 4;

    // x -> fp16; weights -> fp16 hi/lo (x1024)
    cvt_half<<<(nx4 + 255) / 256, 256>>>((const float4*)x, (__half2*)a_p, nx4);
    split_half<<<(nw4 + 255) / 256, 256>>>((const float4*)qkv_w,
        (__half2*)w_hi, (__half2*)w_lo, nw4);
    split_half<<<(np4 + 255) / 256, 256>>>((const float4*)proj_w,
        (__half2*)w2_hi, (__half2*)w2_lo, np4);

    // QKV projection (fp16 x2) -> Q/K/V bf16 hi/lo
    mma_gemm<0><<<dim3(18, 64), 256, GEMM_SMEM>>>(a_p, w_hi, w_lo, qkv_b, nullptr);

    // Flash attention (bf16 x3) -> g_a (fp16, [B,N,C])
    attn_kernel<<<dim3(SEQ / 64, HEADS, BATCH), 128, ATTN_SMEM>>>();

    // Output projection (fp16 x2) -> d_out
    mma_gemm<1><<<dim3(6, 64), 256, GEMM_SMEM>>>(a_p, w2_hi, w2_lo, proj_b, out);
}

// round 16
// speedup vs baseline: 1.4086x; 1.2012x over previous
#include <cuda_runtime.h>
#include <cuda_bf16.h>
#include <cuda_fp16.h>
#include <cstdint>

#define HEADS 12
#define SEQ   2048
#define BATCH 4
#define DH    64
#define CDIM  768
#define MTOT  8192   // BATCH*SEQ
#define NQKV ((size_t)BATCH * HEADS * SEQ * DH)

// ---------------- scratch (allocation-free) ----------------
// attention operands: Q single fp16 (prescaled), K/V fp16 hi/lo
__device__ __align__(16) __half g_q[NQKV];
__device__ __align__(16) __half g_khi[NQKV], g_klo[NQKV];
__device__ __align__(16) __half g_vhi[NQKV], g_vlo[NQKV];
// GEMM activations: single fp16; weights fp16 hi/lo (x1024)
__device__ __align__(16) __half g_a[(size_t)MTOT * CDIM];
__device__ __align__(16) __half g_w_hi[(size_t)3 * CDIM * CDIM];
__device__ __align__(16) __half g_w_lo[(size_t)3 * CDIM * CDIM];
__device__ __align__(16) __half g_w2_hi[(size_t)CDIM * CDIM];
__device__ __align__(16) __half g_w2_lo[(size_t)CDIM * CDIM];

// Q prescale: 1/sqrt(64) * log2(e)  (softmax runs in exp2 domain)
#define QSCALE 0.1803368801111204f
#define WSCALE 1024.0f
#define INVW   (1.0f / 1024.0f)

// ---------------- helpers ----------------
__device__ __forceinline__ uint32_t smem_u32(const void* p) {
    uint32_t a;
    asm("{ .reg .u64 t; cvta.to.shared.u64 t, %1; cvt.u32.u64 %0, t; }" : "=r"(a) : "l"(p));
    return a;
}
__device__ __forceinline__ void ldsm4(uint32_t& r0, uint32_t& r1, uint32_t& r2, uint32_t& r3,
                                      uint32_t addr) {
    asm volatile("ldmatrix.sync.aligned.m8n8.x4.shared.b16 {%0,%1,%2,%3}, [%4];"
                 : "=r"(r0), "=r"(r1), "=r"(r2), "=r"(r3) : "r"(addr));
}
__device__ __forceinline__ void ldsm4t(uint32_t& r0, uint32_t& r1, uint32_t& r2, uint32_t& r3,
                                       uint32_t addr) {
    asm volatile("ldmatrix.sync.aligned.m8n8.x4.trans.shared.b16 {%0,%1,%2,%3}, [%4];"
                 : "=r"(r0), "=r"(r1), "=r"(r2), "=r"(r3) : "r"(addr));
}
// fp16 mma
__device__ __forceinline__ void mma16816h(float* c, const uint32_t* a, uint32_t b0, uint32_t b1) {
    asm volatile("mma.sync.aligned.m16n8k16.row.col.f32.f16.f16.f32 "
                 "{%0,%1,%2,%3}, {%4,%5,%6,%7}, {%8,%9}, {%0,%1,%2,%3};"
                 : "+f"(c[0]), "+f"(c[1]), "+f"(c[2]), "+f"(c[3])
                 : "r"(a[0]), "r"(a[1]), "r"(a[2]), "r"(a[3]), "r"(b0), "r"(b1));
}
__device__ __forceinline__ float ex2f(float x) {
    float y;
    asm("ex2.approx.f32 %0, %1;" : "=f"(y) : "f"(x));
    return y;
}
// pack two floats (lo elem, hi elem) -> fp16x2 register
__device__ __forceinline__ uint32_t packhf(float lo_, float hi_) {
    uint32_t r;
    asm("cvt.rn.f16x2.f32 %0, %1, %2;" : "=r"(r) : "f"(hi_), "f"(lo_));
    return r;
}

#define CP_ASYNC16(dst, src) \
    asm volatile("cp.async.cg.shared.global [%0], [%1], 16;" :: "r"(dst), "l"(src))
#define CP_COMMIT() asm volatile("cp.async.commit_group;")
#define CP_WAIT0()  asm volatile("cp.async.wait_group 0;")

// ---------------------------------------------------------------------------
__global__ void cvt_half(const float4* __restrict__ src, __half2* __restrict__ dst, int n4)
{
    int i = blockIdx.x * 256 + threadIdx.x;
    if (i < n4) {
        float4 v = src[i];
        dst[2 * i]     = __floats2half2_rn(v.x, v.y);
        dst[2 * i + 1] = __floats2half2_rn(v.z, v.w);
    }
}
__global__ void split_half(const float4* __restrict__ src,
                           __half2* __restrict__ hi, __half2* __restrict__ lo, int n4)
{
    int i = blockIdx.x * 256 + threadIdx.x;
    if (i < n4) {
        float4 v = src[i];
        float sx = v.x * WSCALE, sy = v.y * WSCALE, sz = v.z * WSCALE, sw = v.w * WSCALE;
        __half hx = __float2half_rn(sx), hy = __float2half_rn(sy);
        __half hz = __float2half_rn(sz), hw = __float2half_rn(sw);
        hi[2 * i]     = __halves2half2(hx, hy);
        hi[2 * i + 1] = __halves2half2(hz, hw);
        lo[2 * i]     = __floats2half2_rn(sx - __half2float(hx), sy - __half2float(hy));
        lo[2 * i + 1] = __floats2half2_rn(sz - __half2float(hz), sw - __half2float(hw));
    }
}

// ---------------------------------------------------------------------------
// fp16x2 GEMM: C = (A @ (Whi+Wlo)^T) / 1024 + bias. 2 MMA products.
// MODE 0: epilogue -> Q single fp16 (prescaled), K/V fp16 hi/lo, [B,H,N,D].
// MODE 1: fp32 row-major out.
// ---------------------------------------------------------------------------
#define LDT2 40
#define GM_MSZ (128 * LDT2)
#define GA   0
#define GWHI GM_MSZ
#define GWLO (2 * GM_MSZ)
#define GM_BUF (3 * GM_MSZ)
#define GEMM_SMEM (2 * GM_BUF * 2)     // 61440 bytes
#define NCHUNK 24

template <int MODE>
__global__ void __launch_bounds__(256, 2)
mma_gemm(const __half* __restrict__ a, const __half* __restrict__ w_hi,
         const __half* __restrict__ w_lo, const float* __restrict__ bias,
         float* __restrict__ out)
{
    extern __shared__ __half sm[];
    const uint32_t smb = smem_u32(sm);
    const int tid  = threadIdx.x;
    const int lane = tid & 31;
    const int wrp  = tid >> 5;
    const int wm   = wrp & 1;
    const int wn   = wrp >> 1;
    const int rowBase = blockIdx.y * 128;
    const int colBase = blockIdx.x * 128;

    const int a_r = lane & 15;
    const int a_k = (lane >> 4) * 8;
    const int b_r = (lane & 7) + ((lane >> 4) << 3);
    const int b_k = ((lane >> 3) & 1) * 8;

    float acc[4][4][4] = {};

    #define LOAD_CHUNK(kk, buf)                                                       \
        do {                                                                          \
            const uint32_t _bb = smb + (uint32_t)((buf) * GM_BUF) * 2;                \
            _Pragma("unroll")                                                         \
            for (int _i = 0; _i < 2; ++_i) {                                          \
                const int _idx = _i * 256 + tid;                                      \
                const int _r = _idx >> 2, _c = _idx & 3;                              \
                const size_t _ga = (size_t)(rowBase + _r) * CDIM + (kk) + _c * 8;     \
                const size_t _gw = (size_t)(colBase + _r) * CDIM + (kk) + _c * 8;     \
                const uint32_t _so = (uint32_t)(_r * LDT2 + _c * 8) * 2;              \
                CP_ASYNC16(_bb + GA * 2 + _so, a + _ga);                              \
                CP_ASYNC16(_bb + GWHI * 2 + _so, w_hi + _gw);                         \
                CP_ASYNC16(_bb + GWLO * 2 + _so, w_lo + _gw);                         \
            }                                                                         \
        } while (0)

    LOAD_CHUNK(0, 0);
    CP_COMMIT();

    for (int t = 0; t < NCHUNK; ++t) {
        const int buf = t & 1;
        CP_WAIT0();
        __syncthreads();
        if (t < NCHUNK - 1) {
            LOAD_CHUNK((t + 1) * 32, buf ^ 1);
            CP_COMMIT();
        }

        const uint32_t aB  = smb + (uint32_t)(buf * GM_BUF + GA) * 2;
        const uint32_t whB = smb + (uint32_t)(buf * GM_BUF + GWHI) * 2;
        const uint32_t wlB = smb + (uint32_t)(buf * GM_BUF + GWLO) * 2;

        #pragma unroll
        for (int ks = 0; ks < 2; ++ks) {
            uint32_t ah[4][4], wh2[2][4], wl2[2][4];
            #pragma unroll
            for (int mt = 0; mt < 4; ++mt) {
                const uint32_t off =
                    (uint32_t)((wm * 64 + mt * 16 + a_r) * LDT2 + ks * 16 + a_k) * 2;
                ldsm4(ah[mt][0], ah[mt][1], ah[mt][2], ah[mt][3], aB + off);
            }
            #pragma unroll
            for (int np2 = 0; np2 < 2; ++np2) {
                const uint32_t off =
                    (uint32_t)((wn * 32 + np2 * 16 + b_r) * LDT2 + ks * 16 + b_k) * 2;
                ldsm4(wh2[np2][0], wh2[np2][1], wh2[np2][2], wh2[np2][3], whB + off);
                ldsm4(wl2[np2][0], wl2[np2][1], wl2[np2][2], wl2[np2][3], wlB + off);
            }
            #pragma unroll
            for (int mt = 0; mt < 4; ++mt)
                #pragma unroll
                for (int nt = 0; nt < 4; ++nt)
                    mma16816h(acc[mt][nt], ah[mt],
                              wh2[nt >> 1][(nt & 1) * 2], wh2[nt >> 1][(nt & 1) * 2 + 1]);
            #pragma unroll
            for (int mt = 0; mt < 4; ++mt)
                #pragma unroll
                for (int nt = 0; nt < 4; ++nt)
                    mma16816h(acc[mt][nt], ah[mt],
                              wl2[nt >> 1][(nt & 1) * 2], wl2[nt >> 1][(nt & 1) * 2 + 1]);
        }
    }
    #undef LOAD_CHUNK

    #pragma unroll
    for (int mt = 0; mt < 4; ++mt) {
        const int r0 = rowBase + wm * 64 + mt * 16 + (lane >> 2);
        #pragma unroll
        for (int nt = 0; nt < 4; ++nt) {
            const int c = colBase + wn * 32 + nt * 8 + (lane & 3) * 2;
            const float2 bv = *(const float2*)&bias[c];
            float vx0 = acc[mt][nt][0] * INVW + bv.x, vy0 = acc[mt][nt][1] * INVW + bv.y;
            float vx1 = acc[mt][nt][2] * INVW + bv.x, vy1 = acc[mt][nt][3] * INVW + bv.y;
            if (MODE == 0) {
                const int tsel = c / CDIM;
                const int rem  = c - tsel * CDIM;
                const int hh = rem >> 6, d = rem & 63;
                const int m0 = r0, b0 = m0 >> 11, n0 = m0 & 2047;
                const int n1 = n0 + 8;
                const size_t i0 = (((size_t)b0 * HEADS + hh) * SEQ + n0) * DH + d;
                const size_t i1 = (((size_t)b0 * HEADS + hh) * SEQ + n1) * DH + d;
                if (tsel == 0) {
                    *(__half2*)&g_q[i0] = __floats2half2_rn(vx0 * QSCALE, vy0 * QSCALE);
                    *(__half2*)&g_q[i1] = __floats2half2_rn(vx1 * QSCALE, vy1 * QSCALE);
                } else {
                    __half* dh = (tsel == 1) ? g_khi : g_vhi;
                    __half* dl = (tsel == 1) ? g_klo : g_vlo;
                    __half h00 = __float2half_rn(vx0), h01 = __float2half_rn(vy0);
                    __half h10 = __float2half_rn(vx1), h11 = __float2half_rn(vy1);
                    *(__half2*)&dh[i0] = __halves2half2(h00, h01);
                    *(__half2*)&dl[i0] = __floats2half2_rn(vx0 - __half2float(h00),
                                                           vy0 - __half2float(h01));
                    *(__half2*)&dh[i1] = __halves2half2(h10, h11);
                    *(__half2*)&dl[i1] = __floats2half2_rn(vx1 - __half2float(h10),
                                                           vy1 - __half2float(h11));
                }
            } else {
                float2 v0, v1;
                v0.x = vx0; v0.y = vy0; v1.x = vx1; v1.y = vy1;
                *(float2*)&out[(size_t)r0 * CDIM + c] = v0;
                *(float2*)&out[(size_t)(r0 + 8) * CDIM + c] = v1;
            }
        }
    }
}

// ---------------------------------------------------------------------------
// fp16 flash attention (2-product): S = q(kh+kl), O += p(vh+vl).
// 64q x 64k tiles, 128 threads, Q frags register-resident, P direct from S.
// 72KB smem -> 3 CTAs/SM.
// ---------------------------------------------------------------------------
#define QLD 72
#define MSZ (64 * QLD)
#define BKHI 0
#define BKLO MSZ
#define BVHI (2 * MSZ)
#define BVLO (3 * MSZ)
#define BUFSZ (4 * MSZ)
#define ATTN_SMEM (2 * BUFSZ * 2)   // 73728 bytes

__global__ void __launch_bounds__(128, 3)
attn_kernel()
{
    extern __shared__ __half smA[];
    const uint32_t smb = smem_u32(smA);

    const int q0 = blockIdx.x * 64;
    const int h  = blockIdx.y;
    const int b  = blockIdx.z;
    const size_t base = ((size_t)(b * HEADS + h)) * SEQ * DH;

    const int tid  = threadIdx.x;
    const int lane = tid & 31;
    const int wrp  = tid >> 5;
    const int wq   = wrp * 16;

    const int a_r = lane & 15;
    const int a_k = (lane >> 4) * 8;
    const int b_r = (lane & 7) + ((lane >> 4) << 3);
    const int b_k = ((lane >> 3) & 1) * 8;
    const int v_k = (lane & 7) + (((lane >> 3) & 1) << 3);
    const int v_d = (lane >> 4) * 8;
    const int qr  = lane >> 2;
    const int qc  = (lane & 3) * 2;

    // ---- stage Q (single fp16) through buffer 0, extract fragments ----
    uint32_t qf[4][4];
    {
        #pragma unroll
        for (int i = 0; i < 4; ++i) {
            const int idx = i * 128 + tid;     // 0..511
            const int r = idx >> 3, c8 = idx & 7;
            *(uint4*)&smA[r * QLD + c8 * 8] =
                *(const uint4*)&g_q[base + (size_t)(q0 + r) * DH + c8 * 8];
        }
        __syncthreads();
        #pragma unroll
        for (int ks = 0; ks < 4; ++ks)
            ldsm4(qf[ks][0], qf[ks][1], qf[ks][2], qf[ks][3],
                  smb + (uint32_t)((wq + a_r) * QLD + ks * 16 + a_k) * 2);
        __syncthreads();   // Q reads done before cp.async overwrites buffer 0
    }

    #define LOAD_TILE(k0, buf)                                                        \
        do {                                                                          \
            const uint32_t _bb = smb + (uint32_t)((buf) * BUFSZ) * 2;                 \
            const __half* _kh = g_khi + base + (size_t)(k0) * DH;                     \
            const __half* _kl = g_klo + base + (size_t)(k0) * DH;                     \
            const __half* _vh = g_vhi + base + (size_t)(k0) * DH;                     \
            const __half* _vl = g_vlo + base + (size_t)(k0) * DH;                     \
            _Pragma("unroll")                                                         \
            for (int _i = 0; _i < 4; ++_i) {                                          \
                const int _idx = _i * 128 + tid;                                      \
                const int _r = _idx >> 3, _c = _idx & 7;                              \
                const uint32_t _so = (uint32_t)(_r * QLD + _c * 8) * 2;               \
                const size_t _go = (size_t)_r * 64 + _c * 8;                          \
                CP_ASYNC16(_bb + BKHI * 2 + _so, _kh + _go);                          \
                CP_ASYNC16(_bb + BKLO * 2 + _so, _kl + _go);                          \
                CP_ASYNC16(_bb + BVHI * 2 + _so, _vh + _go);                          \
                CP_ASYNC16(_bb + BVLO * 2 + _so, _vl + _go);                          \
            }                                                                         \
        } while (0)

    LOAD_TILE(0, 0);
    CP_COMMIT();

    float m_i[2] = {-1e30f, -1e30f};
    float l_i[2] = {0.f, 0.f};
    float oacc[8][4] = {};

    for (int t = 0; t < 32; ++t) {
        const int buf = t & 1;
        CP_WAIT0();
        __syncthreads();
        if (t < 31) {
            LOAD_TILE((t + 1) * 64, buf ^ 1);
            CP_COMMIT();
        }

        const uint32_t kh = smb + (uint32_t)(buf * BUFSZ + BKHI) * 2;
        const uint32_t kl = smb + (uint32_t)(buf * BUFSZ + BKLO) * 2;
        const uint32_t vh = smb + (uint32_t)(buf * BUFSZ + BVHI) * 2;
        const uint32_t vl = smb + (uint32_t)(buf * BUFSZ + BVLO) * 2;

        // ---- S = q @ (Kh + Kl)^T ----
        float sacc[8][4] = {};
        #pragma unroll
        for (int ks = 0; ks < 4; ++ks) {
            #pragma unroll
            for (int ng = 0; ng < 4; ++ng) {
                uint32_t bh[4], bl[4];
                const uint32_t off = (uint32_t)((ng * 16 + b_r) * QLD + ks * 16 + b_k) * 2;
                ldsm4(bh[0], bh[1], bh[2], bh[3], kh + off);
                ldsm4(bl[0], bl[1], bl[2], bl[3], kl + off);
                mma16816h(sacc[ng * 2 + 0], qf[ks], bh[0], bh[1]);
                mma16816h(sacc[ng * 2 + 1], qf[ks], bh[2], bh[3]);
                mma16816h(sacc[ng * 2 + 0], qf[ks], bl[0], bl[1]);
                mma16816h(sacc[ng * 2 + 1], qf[ks], bl[2], bl[3]);
            }
        }

        // ---- online softmax (exp2 domain, warp-local rows qr, qr+8) ----
        #pragma unroll
        for (int ri = 0; ri < 2; ++ri) {
            float mx = -1e30f;
            #pragma unroll
            for (int nt = 0; nt < 8; ++nt) {
                mx = fmaxf(mx, sacc[nt][ri * 2 + 0]);
                mx = fmaxf(mx, sacc[nt][ri * 2 + 1]);
            }
            mx = fmaxf(mx, __shfl_xor_sync(0xffffffffu, mx, 1));
            mx = fmaxf(mx, __shfl_xor_sync(0xffffffffu, mx, 2));
            const float mn = fmaxf(m_i[ri], mx);
            const float alpha = ex2f(m_i[ri] - mn);
            m_i[ri] = mn;
            float r = 0.f;
            #pragma unroll
            for (int nt = 0; nt < 8; ++nt) {
                float p0 = ex2f(sacc[nt][ri * 2 + 0] - mn);
                float p1 = ex2f(sacc[nt][ri * 2 + 1] - mn);
                sacc[nt][ri * 2 + 0] = p0;
                sacc[nt][ri * 2 + 1] = p1;
                r += p0 + p1;
            }
            r += __shfl_xor_sync(0xffffffffu, r, 1);
            r += __shfl_xor_sync(0xffffffffu, r, 2);
            l_i[ri] = l_i[ri] * alpha + r;
            #pragma unroll
            for (int nt = 0; nt < 8; ++nt) {
                oacc[nt][ri * 2 + 0] *= alpha;
                oacc[nt][ri * 2 + 1] *= alpha;
            }
        }

        // ---- PV: P fp16 direct from sacc, V frags via ldmatrix.trans ----
        #pragma unroll
        for (int ks = 0; ks < 4; ++ks) {
            uint32_t ph[4];
            ph[0] = packhf(sacc[2 * ks][0],     sacc[2 * ks][1]);
            ph[1] = packhf(sacc[2 * ks][2],     sacc[2 * ks][3]);
            ph[2] = packhf(sacc[2 * ks + 1][0], sacc[2 * ks + 1][1]);
            ph[3] = packhf(sacc[2 * ks + 1][2], sacc[2 * ks + 1][3]);
            const uint32_t vrow = (uint32_t)((ks * 16 + v_k) * QLD) * 2;
            #pragma unroll
            for (int ng = 0; ng < 4; ++ng) {
                uint32_t bh[4], bl[4];
                const uint32_t voff = vrow + (uint32_t)(ng * 16 + v_d) * 2;
                ldsm4t(bh[0], bh[1], bh[2], bh[3], vh + voff);
                ldsm4t(bl[0], bl[1], bl[2], bl[3], vl + voff);
                mma16816h(oacc[ng * 2 + 0], ph, bh[0], bh[1]);
                mma16816h(oacc[ng * 2 + 1], ph, bh[2], bh[3]);
                mma16816h(oacc[ng * 2 + 0], ph, bl[0], bl[1]);
                mma16816h(oacc[ng * 2 + 1], ph, bl[2], bl[3]);
            }
        }
    }

    // ---- epilogue: normalize, write single fp16 activation [B,N,C] ----
    const float inv0 = 1.f / l_i[0];
    const float inv1 = 1.f / l_i[1];
    const int row0 = q0 + wq + qr;
    #pragma unroll
    for (int nt = 0; nt < 8; ++nt) {
        const int col = h * DH + nt * 8 + qc;
        const size_t i0 = ((size_t)b * SEQ + row0) * CDIM + col;
        const size_t i1 = ((size_t)b * SEQ + row0 + 8) * CDIM + col;
        *(__half2*)&g_a[i0] = __floats2half2_rn(oacc[nt][0] * inv0, oacc[nt][1] * inv0);
        *(__half2*)&g_a[i1] = __floats2half2_rn(oacc[nt][2] * inv1, oacc[nt][3] * inv1);
    }
    #undef LOAD_TILE
}

// ---------------------------------------------------------------------------
extern "C" void kernel_launch(void* const* d_in, const int* in_sizes, int n_in,
                              void* d_out, int out_size)
{
    const float* x      = (const float*)d_in[0];
    const float* qkv_w  = (const float*)d_in[1];
    const float* qkv_b  = (const float*)d_in[2];
    const float* proj_w = (const float*)d_in[3];
    const float* proj_b = (const float*)d_in[4];
    float* out = (float*)d_out;

    cudaFuncSetAttribute(mma_gemm<0>, cudaFuncAttributeMaxDynamicSharedMemorySize, GEMM_SMEM);
    cudaFuncSetAttribute(mma_gemm<1>, cudaFuncAttributeMaxDynamicSharedMemorySize, GEMM_SMEM);
    cudaFuncSetAttribute(attn_kernel, cudaFuncAttributeMaxDynamicSharedMemorySize, ATTN_SMEM);

    __half *a_p, *w_hi, *w_lo, *w2_hi, *w2_lo;
    cudaGetSymbolAddress((void**)&a_p, g_a);
    cudaGetSymbolAddress((void**)&w_hi, g_w_hi);
    cudaGetSymbolAddress((void**)&w_lo, g_w_lo);
    cudaGetSymbolAddress((void**)&w2_hi, g_w2_hi);
    cudaGetSymbolAddress((void**)&w2_lo, g_w2_lo);

    const int nx4 = MTOT * CDIM / 4;
    const int nw4 = 3 * CDIM * CDIM / 4;
    const int np4 = CDIM * CDIM / 4;

    cvt_half<<<(nx4 + 255) / 256, 256>>>((const float4*)x, (__half2*)a_p, nx4);
    split_half<<<(nw4 + 255) / 256, 256>>>((const float4*)qkv_w,
        (__half2*)w_hi, (__half2*)w_lo, nw4);
    split_half<<<(np4 + 255) / 256, 256>>>((const float4*)proj_w,
        (__half2*)w2_hi, (__half2*)w2_lo, np4);

    // QKV projection (fp16 x2) -> Q (prescaled fp16) / K,V (fp16 hi/lo)
    mma_gemm<0><<<dim3(18, 64), 256, GEMM_SMEM>>>(a_p, w_hi, w_lo, qkv_b, nullptr);

    // Flash attention (fp16 x2) -> g_a (fp16, [B,N,C])
    attn_kernel<<<dim3(SEQ / 64, HEADS, BATCH), 128, ATTN_SMEM>>>();

    // Output projection (fp16 x2) -> d_out
    mma_gemm<1><<<dim3(6, 64), 256, GEMM_SMEM>>>(a_p, w2_hi, w2_lo, proj_b, out);
}

// round 17
// speedup vs baseline: 1.8749x; 1.3310x over previous
#include <cuda_runtime.h>
#include <cuda_bf16.h>
#include <cuda_fp16.h>
#include <cstdint>

#define HEADS 12
#define SEQ   2048
#define BATCH 4
#define DH    64
#define CDIM  768
#define MTOT  8192   // BATCH*SEQ
#define NQKV ((size_t)BATCH * HEADS * SEQ * DH)

// ---------------- scratch (allocation-free) ----------------
// attention operands: Q (prescaled), K, V -- all single fp16
__device__ __align__(16) __half g_q[NQKV];
__device__ __align__(16) __half g_k[NQKV];
__device__ __align__(16) __half g_v[NQKV];
// GEMM activations: single fp16; weights fp16 hi/lo (x1024)
__device__ __align__(16) __half g_a[(size_t)MTOT * CDIM];
__device__ __align__(16) __half g_w_hi[(size_t)3 * CDIM * CDIM];
__device__ __align__(16) __half g_w_lo[(size_t)3 * CDIM * CDIM];
__device__ __align__(16) __half g_w2_hi[(size_t)CDIM * CDIM];
__device__ __align__(16) __half g_w2_lo[(size_t)CDIM * CDIM];

// Q prescale: 1/sqrt(64) * log2(e)  (softmax runs in exp2 domain)
#define QSCALE 0.1803368801111204f
#define WSCALE 1024.0f
#define INVW   (1.0f / 1024.0f)

// ---------------- helpers ----------------
__device__ __forceinline__ uint32_t smem_u32(const void* p) {
    uint32_t a;
    asm("{ .reg .u64 t; cvta.to.shared.u64 t, %1; cvt.u32.u64 %0, t; }" : "=r"(a) : "l"(p));
    return a;
}
__device__ __forceinline__ void ldsm4(uint32_t& r0, uint32_t& r1, uint32_t& r2, uint32_t& r3,
                                      uint32_t addr) {
    asm volatile("ldmatrix.sync.aligned.m8n8.x4.shared.b16 {%0,%1,%2,%3}, [%4];"
                 : "=r"(r0), "=r"(r1), "=r"(r2), "=r"(r3) : "r"(addr));
}
__device__ __forceinline__ void ldsm4t(uint32_t& r0, uint32_t& r1, uint32_t& r2, uint32_t& r3,
                                       uint32_t addr) {
    asm volatile("ldmatrix.sync.aligned.m8n8.x4.trans.shared.b16 {%0,%1,%2,%3}, [%4];"
                 : "=r"(r0), "=r"(r1), "=r"(r2), "=r"(r3) : "r"(addr));
}
__device__ __forceinline__ void mma16816h(float* c, const uint32_t* a, uint32_t b0, uint32_t b1) {
    asm volatile("mma.sync.aligned.m16n8k16.row.col.f32.f16.f16.f32 "
                 "{%0,%1,%2,%3}, {%4,%5,%6,%7}, {%8,%9}, {%0,%1,%2,%3};"
                 : "+f"(c[0]), "+f"(c[1]), "+f"(c[2]), "+f"(c[3])
                 : "r"(a[0]), "r"(a[1]), "r"(a[2]), "r"(a[3]), "r"(b0), "r"(b1));
}
__device__ __forceinline__ float ex2f(float x) {
    float y;
    asm("ex2.approx.f32 %0, %1;" : "=f"(y) : "f"(x));
    return y;
}
__device__ __forceinline__ uint32_t packhf(float lo_, float hi_) {
    uint32_t r;
    asm("cvt.rn.f16x2.f32 %0, %1, %2;" : "=r"(r) : "f"(hi_), "f"(lo_));
    return r;
}

#define CP_ASYNC16(dst, src) \
    asm volatile("cp.async.cg.shared.global [%0], [%1], 16;" :: "r"(dst), "l"(src))
#define CP_COMMIT() asm volatile("cp.async.commit_group;")
#define CP_WAIT0()  asm volatile("cp.async.wait_group 0;")

// ---------------------------------------------------------------------------
__global__ void cvt_half(const float4* __restrict__ src, __half2* __restrict__ dst, int n4)
{
    int i = blockIdx.x * 256 + threadIdx.x;
    if (i < n4) {
        float4 v = src[i];
        dst[2 * i]     = __floats2half2_rn(v.x, v.y);
        dst[2 * i + 1] = __floats2half2_rn(v.z, v.w);
    }
}
__global__ void split_half(const float4* __restrict__ src,
                           __half2* __restrict__ hi, __half2* __restrict__ lo, int n4)
{
    int i = blockIdx.x * 256 + threadIdx.x;
    if (i < n4) {
        float4 v = src[i];
        float sx = v.x * WSCALE, sy = v.y * WSCALE, sz = v.z * WSCALE, sw = v.w * WSCALE;
        __half hx = __float2half_rn(sx), hy = __float2half_rn(sy);
        __half hz = __float2half_rn(sz), hw = __float2half_rn(sw);
        hi[2 * i]     = __halves2half2(hx, hy);
        hi[2 * i + 1] = __halves2half2(hz, hw);
        lo[2 * i]     = __floats2half2_rn(sx - __half2float(hx), sy - __half2float(hy));
        lo[2 * i + 1] = __floats2half2_rn(sz - __half2float(hz), sw - __half2float(hw));
    }
}

// ---------------------------------------------------------------------------
// fp16x2 GEMM: C = (A @ (Whi+Wlo)^T) / 1024 + bias. 2 MMA products.
// MODE 0: epilogue -> Q (prescaled) / K / V single fp16, [B,H,N,D].
// MODE 1: fp32 row-major out.
// ---------------------------------------------------------------------------
#define LDT2 40
#define GM_MSZ (128 * LDT2)
#define GA   0
#define GWHI GM_MSZ
#define GWLO (2 * GM_MSZ)
#define GM_BUF (3 * GM_MSZ)
#define GEMM_SMEM (2 * GM_BUF * 2)     // 61440 bytes
#define NCHUNK 24

template <int MODE>
__global__ void __launch_bounds__(256, 2)
mma_gemm(const __half* __restrict__ a, const __half* __restrict__ w_hi,
         const __half* __restrict__ w_lo, const float* __restrict__ bias,
         float* __restrict__ out)
{
    extern __shared__ __half sm[];
    const uint32_t smb = smem_u32(sm);
    const int tid  = threadIdx.x;
    const int lane = tid & 31;
    const int wrp  = tid >> 5;
    const int wm   = wrp & 1;
    const int wn   = wrp >> 1;
    const int rowBase = blockIdx.y * 128;
    const int colBase = blockIdx.x * 128;

    const int a_r = lane & 15;
    const int a_k = (lane >> 4) * 8;
    const int b_r = (lane & 7) + ((lane >> 4) << 3);
    const int b_k = ((lane >> 3) & 1) * 8;

    float acc[4][4][4] = {};

    #define LOAD_CHUNK(kk, buf)                                                       \
        do {                                                                          \
            const uint32_t _bb = smb + (uint32_t)((buf) * GM_BUF) * 2;                \
            _Pragma("unroll")                                                         \
            for (int _i = 0; _i < 2; ++_i) {                                          \
                const int _idx = _i * 256 + tid;                                      \
                const int _r = _idx >> 2, _c = _idx & 3;                              \
                const size_t _ga = (size_t)(rowBase + _r) * CDIM + (kk) + _c * 8;     \
                const size_t _gw = (size_t)(colBase + _r) * CDIM + (kk) + _c * 8;     \
                const uint32_t _so = (uint32_t)(_r * LDT2 + _c * 8) * 2;              \
                CP_ASYNC16(_bb + GA * 2 + _so, a + _ga);                              \
                CP_ASYNC16(_bb + GWHI * 2 + _so, w_hi + _gw);                         \
                CP_ASYNC16(_bb + GWLO * 2 + _so, w_lo + _gw);                         \
            }                                                                         \
        } while (0)

    LOAD_CHUNK(0, 0);
    CP_COMMIT();

    for (int t = 0; t < NCHUNK; ++t) {
        const int buf = t & 1;
        CP_WAIT0();
        __syncthreads();
        if (t < NCHUNK - 1) {
            LOAD_CHUNK((t + 1) * 32, buf ^ 1);
            CP_COMMIT();
        }

        const uint32_t aB  = smb + (uint32_t)(buf * GM_BUF + GA) * 2;
        const uint32_t whB = smb + (uint32_t)(buf * GM_BUF + GWHI) * 2;
        const uint32_t wlB = smb + (uint32_t)(buf * GM_BUF + GWLO) * 2;

        #pragma unroll
        for (int ks = 0; ks < 2; ++ks) {
            uint32_t ah[4][4], wh2[2][4], wl2[2][4];
            #pragma unroll
            for (int mt = 0; mt < 4; ++mt) {
                const uint32_t off =
                    (uint32_t)((wm * 64 + mt * 16 + a_r) * LDT2 + ks * 16 + a_k) * 2;
                ldsm4(ah[mt][0], ah[mt][1], ah[mt][2], ah[mt][3], aB + off);
            }
            #pragma unroll
            for (int np2 = 0; np2 < 2; ++np2) {
                const uint32_t off =
                    (uint32_t)((wn * 32 + np2 * 16 + b_r) * LDT2 + ks * 16 + b_k) * 2;
                ldsm4(wh2[np2][0], wh2[np2][1], wh2[np2][2], wh2[np2][3], whB + off);
                ldsm4(wl2[np2][0], wl2[np2][1], wl2[np2][2], wl2[np2][3], wlB + off);
            }
            #pragma unroll
            for (int mt = 0; mt < 4; ++mt)
                #pragma unroll
                for (int nt = 0; nt < 4; ++nt)
                    mma16816h(acc[mt][nt], ah[mt],
                              wh2[nt >> 1][(nt & 1) * 2], wh2[nt >> 1][(nt & 1) * 2 + 1]);
            #pragma unroll
            for (int mt = 0; mt < 4; ++mt)
                #pragma unroll
                for (int nt = 0; nt < 4; ++nt)
                    mma16816h(acc[mt][nt], ah[mt],
                              wl2[nt >> 1][(nt & 1) * 2], wl2[nt >> 1][(nt & 1) * 2 + 1]);
        }
    }
    #undef LOAD_CHUNK

    #pragma unroll
    for (int mt = 0; mt < 4; ++mt) {
        const int r0 = rowBase + wm * 64 + mt * 16 + (lane >> 2);
        #pragma unroll
        for (int nt = 0; nt < 4; ++nt) {
            const int c = colBase + wn * 32 + nt * 8 + (lane & 3) * 2;
            const float2 bv = *(const float2*)&bias[c];
            float vx0 = acc[mt][nt][0] * INVW + bv.x, vy0 = acc[mt][nt][1] * INVW + bv.y;
            float vx1 = acc[mt][nt][2] * INVW + bv.x, vy1 = acc[mt][nt][3] * INVW + bv.y;
            if (MODE == 0) {
                const int tsel = c / CDIM;
                const int rem  = c - tsel * CDIM;
                const int hh = rem >> 6, d = rem & 63;
                const int m0 = r0, b0 = m0 >> 11, n0 = m0 & 2047;
                const int n1 = n0 + 8;
                const size_t i0 = (((size_t)b0 * HEADS + hh) * SEQ + n0) * DH + d;
                const size_t i1 = (((size_t)b0 * HEADS + hh) * SEQ + n1) * DH + d;
                if (tsel == 0) {
                    *(__half2*)&g_q[i0] = __floats2half2_rn(vx0 * QSCALE, vy0 * QSCALE);
                    *(__half2*)&g_q[i1] = __floats2half2_rn(vx1 * QSCALE, vy1 * QSCALE);
                } else {
                    __half* dst = (tsel == 1) ? g_k : g_v;
                    *(__half2*)&dst[i0] = __floats2half2_rn(vx0, vy0);
                    *(__half2*)&dst[i1] = __floats2half2_rn(vx1, vy1);
                }
            } else {
                float2 v0, v1;
                v0.x = vx0; v0.y = vy0; v1.x = vx1; v1.y = vy1;
                *(float2*)&out[(size_t)r0 * CDIM + c] = v0;
                *(float2*)&out[(size_t)(r0 + 8) * CDIM + c] = v1;
            }
        }
    }
}

// ---------------------------------------------------------------------------
// fp16 flash attention (1 product per GEMM): S = q@k^T, O += p@v.
// 64q x 64k tiles, 128 threads, Q frags register-resident, P direct from S.
// 36.9KB smem -> 4 CTAs/SM.
// ---------------------------------------------------------------------------
#define QLD 72
#define MSZ (64 * QLD)
#define BK 0
#define BV MSZ
#define BUFSZ (2 * MSZ)
#define ATTN_SMEM (2 * BUFSZ * 2)   // 36864 bytes

__global__ void __launch_bounds__(128, 4)
attn_kernel()
{
    extern __shared__ __half smA[];
    const uint32_t smb = smem_u32(smA);

    const int q0 = blockIdx.x * 64;
    const int h  = blockIdx.y;
    const int b  = blockIdx.z;
    const size_t base = ((size_t)(b * HEADS + h)) * SEQ * DH;

    const int tid  = threadIdx.x;
    const int lane = tid & 31;
    const int wrp  = tid >> 5;
    const int wq   = wrp * 16;

    const int a_r = lane & 15;
    const int a_k = (lane >> 4) * 8;
    const int b_r = (lane & 7) + ((lane >> 4) << 3);
    const int b_k = ((lane >> 3) & 1) * 8;
    const int v_k = (lane & 7) + (((lane >> 3) & 1) << 3);
    const int v_d = (lane >> 4) * 8;
    const int qr  = lane >> 2;
    const int qc  = (lane & 3) * 2;

    // ---- stage Q (single fp16) through buffer 0, extract fragments ----
    uint32_t qf[4][4];
    {
        #pragma unroll
        for (int i = 0; i < 4; ++i) {
            const int idx = i * 128 + tid;     // 0..511
            const int r = idx >> 3, c8 = idx & 7;
            *(uint4*)&smA[r * QLD + c8 * 8] =
                *(const uint4*)&g_q[base + (size_t)(q0 + r) * DH + c8 * 8];
        }
        __syncthreads();
        #pragma unroll
        for (int ks = 0; ks < 4; ++ks)
            ldsm4(qf[ks][0], qf[ks][1], qf[ks][2], qf[ks][3],
                  smb + (uint32_t)((wq + a_r) * QLD + ks * 16 + a_k) * 2);
        __syncthreads();   // Q reads done before cp.async overwrites buffer 0
    }

    #define LOAD_TILE(k0, buf)                                                        \
        do {                                                                          \
            const uint32_t _bb = smb + (uint32_t)((buf) * BUFSZ) * 2;                 \
            const __half* _k = g_k + base + (size_t)(k0) * DH;                        \
            const __half* _v = g_v + base + (size_t)(k0) * DH;                        \
            _Pragma("unroll")                                                         \
            for (int _i = 0; _i < 4; ++_i) {                                          \
                const int _idx = _i * 128 + tid;                                      \
                const int _r = _idx >> 3, _c = _idx & 7;                              \
                const uint32_t _so = (uint32_t)(_r * QLD + _c * 8) * 2;               \
                const size_t _go = (size_t)_r * 64 + _c * 8;                          \
                CP_ASYNC16(_bb + BK * 2 + _so, _k + _go);                             \
                CP_ASYNC16(_bb + BV * 2 + _so, _v + _go);                             \
            }                                                                         \
        } while (0)

    LOAD_TILE(0, 0);
    CP_COMMIT();

    float m_i[2] = {-1e30f, -1e30f};
    float l_i[2] = {0.f, 0.f};
    float oacc[8][4] = {};

    for (int t = 0; t < 32; ++t) {
        const int buf = t & 1;
        CP_WAIT0();
        __syncthreads();
        if (t < 31) {
            LOAD_TILE((t + 1) * 64, buf ^ 1);
            CP_COMMIT();
        }

        const uint32_t kB = smb + (uint32_t)(buf * BUFSZ + BK) * 2;
        const uint32_t vB = smb + (uint32_t)(buf * BUFSZ + BV) * 2;

        // ---- S = q @ k^T ----
        float sacc[8][4] = {};
        #pragma unroll
        for (int ks = 0; ks < 4; ++ks) {
            #pragma unroll
            for (int ng = 0; ng < 4; ++ng) {
                uint32_t bf[4];
                ldsm4(bf[0], bf[1], bf[2], bf[3],
                      kB + (uint32_t)((ng * 16 + b_r) * QLD + ks * 16 + b_k) * 2);
                mma16816h(sacc[ng * 2 + 0], qf[ks], bf[0], bf[1]);
                mma16816h(sacc[ng * 2 + 1], qf[ks], bf[2], bf[3]);
            }
        }

        // ---- online softmax (exp2 domain, warp-local rows qr, qr+8) ----
        #pragma unroll
        for (int ri = 0; ri < 2; ++ri) {
            float mx = -1e30f;
            #pragma unroll
            for (int nt = 0; nt < 8; ++nt) {
                mx = fmaxf(mx, sacc[nt][ri * 2 + 0]);
                mx = fmaxf(mx, sacc[nt][ri * 2 + 1]);
            }
            mx = fmaxf(mx, __shfl_xor_sync(0xffffffffu, mx, 1));
            mx = fmaxf(mx, __shfl_xor_sync(0xffffffffu, mx, 2));
            const float mn = fmaxf(m_i[ri], mx);
            const float alpha = ex2f(m_i[ri] - mn);
            m_i[ri] = mn;
            float r = 0.f;
            #pragma unroll
            for (int nt = 0; nt < 8; ++nt) {
                float p0 = ex2f(sacc[nt][ri * 2 + 0] - mn);
                float p1 = ex2f(sacc[nt][ri * 2 + 1] - mn);
                sacc[nt][ri * 2 + 0] = p0;
                sacc[nt][ri * 2 + 1] = p1;
                r += p0 + p1;
            }
            r += __shfl_xor_sync(0xffffffffu, r, 1);
            r += __shfl_xor_sync(0xffffffffu, r, 2);
            l_i[ri] = l_i[ri] * alpha + r;
            #pragma unroll
            for (int nt = 0; nt < 8; ++nt) {
                oacc[nt][ri * 2 + 0] *= alpha;
                oacc[nt][ri * 2 + 1] *= alpha;
            }
        }

        // ---- PV: P fp16 direct from sacc, V frags via ldmatrix.trans ----
        #pragma unroll
        for (int ks = 0; ks < 4; ++ks) {
            uint32_t ph[4];
            ph[0] = packhf(sacc[2 * ks][0],     sacc[2 * ks][1]);
            ph[1] = packhf(sacc[2 * ks][2],     sacc[2 * ks][3]);
            ph[2] = packhf(sacc[2 * ks + 1][0], sacc[2 * ks + 1][1]);
            ph[3] = packhf(sacc[2 * ks + 1][2], sacc[2 * ks + 1][3]);
            const uint32_t vrow = (uint32_t)((ks * 16 + v_k) * QLD) * 2;
            #pragma unroll
            for (int ng = 0; ng < 4; ++ng) {
                uint32_t bf[4];
                ldsm4t(bf[0], bf[1], bf[2], bf[3], vB + vrow + (uint32_t)(ng * 16 + v_d) * 2);
                mma16816h(oacc[ng * 2 + 0], ph, bf[0], bf[1]);
                mma16816h(oacc[ng * 2 + 1], ph, bf[2], bf[3]);
            }
        }
    }

    // ---- epilogue: normalize, write single fp16 activation [B,N,C] ----
    const float inv0 = 1.f / l_i[0];
    const float inv1 = 1.f / l_i[1];
    const int row0 = q0 + wq + qr;
    #pragma unroll
    for (int nt = 0; nt < 8; ++nt) {
        const int col = h * DH + nt * 8 + qc;
        const size_t i0 = ((size_t)b * SEQ + row0) * CDIM + col;
        const size_t i1 = ((size_t)b * SEQ + row0 + 8) * CDIM + col;
        *(__half2*)&g_a[i0] = __floats2half2_rn(oacc[nt][0] * inv0, oacc[nt][1] * inv0);
        *(__half2*)&g_a[i1] = __floats2half2_rn(oacc[nt][2] * inv1, oacc[nt][3] * inv1);
    }
    #undef LOAD_TILE
}

// ---------------------------------------------------------------------------
extern "C" void kernel_launch(void* const* d_in, const int* in_sizes, int n_in,
                              void* d_out, int out_size)
{
    const float* x      = (const float*)d_in[0];
    const float* qkv_w  = (const float*)d_in[1];
    const float* qkv_b  = (const float*)d_in[2];
    const float* proj_w = (const float*)d_in[3];
    const float* proj_b = (const float*)d_in[4];
    float* out = (float*)d_out;

    cudaFuncSetAttribute(mma_gemm<0>, cudaFuncAttributeMaxDynamicSharedMemorySize, GEMM_SMEM);
    cudaFuncSetAttribute(mma_gemm<1>, cudaFuncAttributeMaxDynamicSharedMemorySize, GEMM_SMEM);
    cudaFuncSetAttribute(attn_kernel, cudaFuncAttributeMaxDynamicSharedMemorySize, ATTN_SMEM);

    __half *a_p, *w_hi, *w_lo, *w2_hi, *w2_lo;
    cudaGetSymbolAddress((void**)&a_p, g_a);
    cudaGetSymbolAddress((void**)&w_hi, g_w_hi);
    cudaGetSymbolAddress((void**)&w_lo, g_w_lo);
    cudaGetSymbolAddress((void**)&w2_hi, g_w2_hi);
    cudaGetSymbolAddress((void**)&w2_lo, g_w2_lo);

    const int nx4 = MTOT * CDIM / 4;
    const int nw4 = 3 * CDIM * CDIM / 4;
    const int np4 = CDIM * CDIM / 4;

    cvt_half<<<(nx4 + 255) / 256, 256>>>((const float4*)x, (__half2*)a_p, nx4);
    split_half<<<(nw4 + 255) / 256, 256>>>((const float4*)qkv_w,
        (__half2*)w_hi, (__half2*)w_lo, nw4);
    split_half<<<(np4 + 255) / 256, 256>>>((const float4*)proj_w,
        (__half2*)w2_hi, (__half2*)w2_lo, np4);

    // QKV projection (fp16 x2) -> Q (prescaled) / K / V single fp16
    mma_gemm<0><<<dim3(18, 64), 256, GEMM_SMEM>>>(a_p, w_hi, w_lo, qkv_b, nullptr);

    // Flash attention (fp16 x1) -> g_a (fp16, [B,N,C])
    attn_kernel<<<dim3(SEQ / 64, HEADS, BATCH), 128, ATTN_SMEM>>>();

    // Output projection (fp16 x2) -> d_out
    mma_gemm<1><<<dim3(6, 64), 256, GEMM_SMEM>>>(a_p, w2_hi, w2_lo, proj_b, out);
}